// round 8
// baseline (speedup 1.0000x reference)
#include <cuda_runtime.h>
#include <cuda_bf16.h>
#include <mma.h>
#include <cuda_pipeline.h>
#include <math.h>

using namespace nvcuda;

// Problem dims
#define MROWS 16384            // B*S
#define DDIM  2048             // D
#define MSZ   ((size_t)MROWS * DDIM)
#define WSZ   ((size_t)DDIM * DDIM)

// ---------------- device scratch (allocation-free rule) ------------------------
__device__ __nv_bfloat16 g_Ah[MSZ];
__device__ __nv_bfloat16 g_Al[MSZ];
__device__ __nv_bfloat16 g_Hh[MSZ];
__device__ __nv_bfloat16 g_Hl[MSZ];
__device__ __nv_bfloat16 g_Wh[5 * WSZ];    // weight splits [K,N] row-major
__device__ __nv_bfloat16 g_Wl[5 * WSZ];
__device__ float g_Q [MSZ];
__device__ float g_K [MSZ];
__device__ float g_V [MSZ];
__device__ float g_X1[MSZ];

// ---------------- fused split: X + all 5 weights in ONE launch ------------------
// blockIdx.y: 0 = X (nA elems), 1..5 = weight i-1 (nW elems). float4-vectorized.
__global__ void __launch_bounds__(256)
split_all_kernel(const float* __restrict__ X,
                 const float* __restrict__ W0, const float* __restrict__ W1,
                 const float* __restrict__ W2, const float* __restrict__ W3,
                 const float* __restrict__ W4,
                 __nv_bfloat16* __restrict__ Ah, __nv_bfloat16* __restrict__ Al,
                 __nv_bfloat16* __restrict__ Wh, __nv_bfloat16* __restrict__ Wl)
{
    const int which = blockIdx.y;
    const float* src;
    __nv_bfloat16 *oh, *ol;
    int n4;
    if (which == 0) {
        src = X; oh = Ah; ol = Al; n4 = (MROWS * DDIM) / 4;
    } else {
        const float* Ws[5] = {W0, W1, W2, W3, W4};
        src = Ws[which - 1];
        oh = Wh + (size_t)(which - 1) * WSZ;
        ol = Wl + (size_t)(which - 1) * WSZ;
        n4 = (DDIM * DDIM) / 4;
    }
    int i = blockIdx.x * 256 + threadIdx.x;
    if (i >= n4) return;
    float4 v = ((const float4*)src)[i];
    __nv_bfloat162 h0 = {__float2bfloat16(v.x), __float2bfloat16(v.y)};
    __nv_bfloat162 h1 = {__float2bfloat16(v.z), __float2bfloat16(v.w)};
    __nv_bfloat162 l0 = {__float2bfloat16(v.x - __bfloat162float(h0.x)),
                         __float2bfloat16(v.y - __bfloat162float(h0.y))};
    __nv_bfloat162 l1 = {__float2bfloat16(v.z - __bfloat162float(h1.x)),
                         __float2bfloat16(v.w - __bfloat162float(h1.y))};
    ((__nv_bfloat162*)oh)[2 * i]     = h0;
    ((__nv_bfloat162*)oh)[2 * i + 1] = h1;
    ((__nv_bfloat162*)ol)[2 * i]     = l0;
    ((__nv_bfloat162*)ol)[2 * i + 1] = l1;
}

// ================= bf16x3 GEMM (HMMA), fragment-double-buffered ================
// C[M,N] = (Ah+Al)(Bh+Bl), fp32 accum. Logical K3 = 3*2048:
//   seg0 = Ah*Bh, seg1 = Al*Bh, seg2 = Ah*Bl   (AlBl dropped, ~2^-16 rel)
constexpr int BM = 128, BN = 256, BK = 32;
constexpr int NSTG = 3;
constexpr int APAD = 8,  LDA = BK + APAD;     // 40
constexpr int BPAD = 8,  LDB = BN + BPAD;     // 264
constexpr int A_BYTES = BM * LDA * 2;         // 10240
constexpr int B_BYTES = BK * LDB * 2;         // 16896
constexpr int STG_BYTES = A_BYTES + B_BYTES;  // 27136
constexpr int GEMM_SMEM = NSTG * STG_BYTES;   // 81408

template<int EPI>
__global__ void __launch_bounds__(256, 1)
gemm_bf16x3(const __nv_bfloat16* __restrict__ Ah, const __nv_bfloat16* __restrict__ Al,
            const __nv_bfloat16* __restrict__ Bh, const __nv_bfloat16* __restrict__ Bl,
            const float* __restrict__ bias,
            float* __restrict__ C,
            __nv_bfloat16* __restrict__ Oh, __nv_bfloat16* __restrict__ Ol)
{
    constexpr int K = DDIM, N = DDIM;
    extern __shared__ char dsm[];

    const int tid  = threadIdx.x;
    const int warp = tid >> 5, lane = tid & 31;
    const int wr = warp >> 2;          // 0..1 -> 64-row slab
    const int wc = warp & 3;           // 0..3 -> 64-col slab
    const int m0 = blockIdx.y * BM, n0 = blockIdx.x * BN;

    wmma::fragment<wmma::accumulator, 16, 16, 16, float> acc[4][4];
    #pragma unroll
    for (int i = 0; i < 4; i++)
        #pragma unroll
        for (int j = 0; j < 4; j++) wmma::fill_fragment(acc[i][j], 0.0f);

    auto load_stage = [&](int s, int kt) {
        int seg = (kt >= 2 * K) ? 2 : ((kt >= K) ? 1 : 0);
        int kk  = kt - seg * K;
        const __nv_bfloat16* Ap = (seg == 1) ? Al : Ah;
        const __nv_bfloat16* Bp = (seg == 2) ? Bl : Bh;
        __nv_bfloat16* sA = (__nv_bfloat16*)(dsm + s * STG_BYTES);
        __nv_bfloat16* sB = (__nv_bfloat16*)(dsm + s * STG_BYTES + A_BYTES);
        #pragma unroll
        for (int r = 0; r < 2; r++) {              // A: 128x32 = 512 x 16B
            int idx = tid + r * 256;
            int row = idx >> 2, c8 = (idx & 3) * 8;
            __pipeline_memcpy_async(sA + row * LDA + c8,
                                    Ap + (size_t)(m0 + row) * K + kk + c8, 16);
        }
        #pragma unroll
        for (int r = 0; r < 4; r++) {              // B: 32x256 = 1024 x 16B
            int idx = tid + r * 256;
            int row = idx >> 5, c8 = (idx & 31) * 8;
            __pipeline_memcpy_async(sB + row * LDB + c8,
                                    Bp + (size_t)(kk + row) * N + n0 + c8, 16);
        }
    };

    const int nIter = (3 * K) / BK;   // 192
    load_stage(0, 0);             __pipeline_commit();
    load_stage(1, BK);            __pipeline_commit();

    for (int it = 0; it < nIter; ++it) {
        int cur = it % NSTG;
        __pipeline_wait_prior(1);          // stage `it` resident
        __syncthreads();                   // prev compute done before overwrite
        if (it + 2 < nIter) load_stage((it + 2) % NSTG, (it + 2) * BK);
        __pipeline_commit();

        const __nv_bfloat16* sA = (const __nv_bfloat16*)(dsm + cur * STG_BYTES);
        const __nv_bfloat16* sB = (const __nv_bfloat16*)(dsm + cur * STG_BYTES + A_BYTES);

        // fragment double-buffer: load both k16 slices up front so the LDSM of
        // slice 1 overlaps the HMMA stream of slice 0.
        wmma::fragment<wmma::matrix_a, 16, 16, 16, __nv_bfloat16, wmma::row_major> af[2][4];
        wmma::fragment<wmma::matrix_b, 16, 16, 16, __nv_bfloat16, wmma::row_major> bf[2][4];
        #pragma unroll
        for (int h = 0; h < 2; h++) {
            #pragma unroll
            for (int i = 0; i < 4; i++)
                wmma::load_matrix_sync(af[h][i], sA + (wr * 64 + i * 16) * LDA + h * 16, LDA);
            #pragma unroll
            for (int j = 0; j < 4; j++)
                wmma::load_matrix_sync(bf[h][j], sB + (h * 16) * LDB + wc * 64 + j * 16, LDB);
        }
        #pragma unroll
        for (int h = 0; h < 2; h++)
            #pragma unroll
            for (int i = 0; i < 4; i++)
                #pragma unroll
                for (int j = 0; j < 4; j++)
                    wmma::mma_sync(acc[i][j], af[h][i], bf[h][j], acc[i][j]);
    }
    __syncthreads();

    // epilogue: per-warp smem staging, coalesced stores
    float* buf = (float*)dsm + warp * 272;
    #pragma unroll
    for (int i = 0; i < 4; i++) {
        #pragma unroll
        for (int j = 0; j < 4; j++) {
            wmma::store_matrix_sync(buf, acc[i][j], 16, wmma::mem_row_major);
            __syncwarp();
            const int gr = m0 + wr * 64 + i * 16;
            const int gc = n0 + wc * 64 + j * 16;
            const int r  = lane >> 1, ch = (lane & 1) * 8;
            #pragma unroll
            for (int e = 0; e < 8; e++) {
                int cc = ch + e;
                float v = buf[r * 16 + cc] + bias[gc + cc];
                size_t o = (size_t)(gr + r) * N + gc + cc;
                if (EPI == 0) {
                    C[o] = v;
                } else {
                    float gl = v * normcdff(v);            // exact GELU
                    __nv_bfloat16 hh = __float2bfloat16(gl);
                    Oh[o] = hh;
                    Ol[o] = __float2bfloat16(gl - __bfloat162float(hh));
                }
            }
            __syncwarp();
        }
    }
}

// ---------------- per-token head-attention + residual + LN1 (float4) -----------
__global__ void __launch_bounds__(128)
attn_ln1_kernel(const float* __restrict__ Q, const float* __restrict__ Kk,
                const float* __restrict__ V, const float* __restrict__ X,
                const float* __restrict__ g1, const float* __restrict__ be1,
                float* __restrict__ X1,
                __nv_bfloat16* __restrict__ Oh, __nv_bfloat16* __restrict__ Ol)
{
    __shared__ float sq[16 * 129], sk[16 * 129], sv[16 * 129];
    __shared__ float satt[16][16];
    __shared__ float red[8];
    const int t = blockIdx.x, tid = threadIdx.x;
    const size_t base4 = (size_t)t * (DDIM / 4);

    const float4* Q4 = (const float4*)Q;
    const float4* K4 = (const float4*)Kk;
    const float4* V4 = (const float4*)V;
    const float4* X4 = (const float4*)X;

    #pragma unroll
    for (int it = 0; it < 4; it++) {
        int i4 = tid + it * 128;                 // 0..511 float4 per array
        int e = i4 * 4, h = e >> 7, d = e & 127, o = h * 129 + d;
        float4 q = Q4[base4 + i4], k = K4[base4 + i4], v = V4[base4 + i4];
        sq[o] = q.x; sq[o+1] = q.y; sq[o+2] = q.z; sq[o+3] = q.w;
        sk[o] = k.x; sk[o+1] = k.y; sk[o+2] = k.z; sk[o+3] = k.w;
        sv[o] = v.x; sv[o+1] = v.y; sv[o+2] = v.z; sv[o+3] = v.w;
    }
    __syncthreads();

    #pragma unroll
    for (int p = tid; p < 256; p += 128) {
        int h = p >> 4, tt = p & 15;
        const float* qp = sq + h * 129;
        const float* kp = sk + tt * 129;
        float s = 0.f;
        #pragma unroll
        for (int d = 0; d < 128; d++) s += qp[d] * kp[d];
        satt[h][tt] = s * 0.08838834764831845f;     // 1/sqrt(128)
    }
    __syncthreads();

    if (tid < 16) {
        float mx = -1e30f;
        #pragma unroll
        for (int j = 0; j < 16; j++) mx = fmaxf(mx, satt[tid][j]);
        float sum = 0.f;
        #pragma unroll
        for (int j = 0; j < 16; j++) { float e = expf(satt[tid][j] - mx); satt[tid][j] = e; sum += e; }
        float inv = 1.f / sum;
        #pragma unroll
        for (int j = 0; j < 16; j++) satt[tid][j] *= inv;
    }
    __syncthreads();

    float4 xp[4];
    float ls = 0.f, lq = 0.f;
    #pragma unroll
    for (int it = 0; it < 4; it++) {
        int i4 = tid + it * 128;
        int e = i4 * 4, h = e >> 7, d = e & 127;
        float4 xv = X4[base4 + i4];
        float y0 = 0.f, y1 = 0.f, y2 = 0.f, y3 = 0.f;
        #pragma unroll
        for (int tt = 0; tt < 16; tt++) {
            float p = satt[h][tt];
            const float* vp = sv + tt * 129 + d;
            y0 += p * vp[0]; y1 += p * vp[1]; y2 += p * vp[2]; y3 += p * vp[3];
        }
        xv.x += y0; xv.y += y1; xv.z += y2; xv.w += y3;
        xp[it] = xv;
        ls += xv.x + xv.y + xv.z + xv.w;
        lq += xv.x * xv.x + xv.y * xv.y + xv.z * xv.z + xv.w * xv.w;
    }
    #pragma unroll
    for (int off = 16; off; off >>= 1) {
        ls += __shfl_xor_sync(0xffffffffu, ls, off);
        lq += __shfl_xor_sync(0xffffffffu, lq, off);
    }
    if ((tid & 31) == 0) { red[tid >> 5] = ls; red[4 + (tid >> 5)] = lq; }
    __syncthreads();
    float S  = red[0] + red[1] + red[2] + red[3];
    float Qs = red[4] + red[5] + red[6] + red[7];
    float mean = S * (1.0f / DDIM);
    float var  = Qs * (1.0f / DDIM) - mean * mean;
    float inv  = rsqrtf(var + 1e-5f);

    const float4* G4 = (const float4*)g1;
    const float4* Be4 = (const float4*)be1;
    #pragma unroll
    for (int it = 0; it < 4; it++) {
        int i4 = tid + it * 128;
        float4 g = G4[i4], be = Be4[i4];
        float4 xv = xp[it];
        float4 v;
        v.x = (xv.x - mean) * inv * g.x + be.x;
        v.y = (xv.y - mean) * inv * g.y + be.y;
        v.z = (xv.z - mean) * inv * g.z + be.z;
        v.w = (xv.w - mean) * inv * g.w + be.w;
        ((float4*)X1)[base4 + i4] = v;
        __nv_bfloat162 h0 = {__float2bfloat16(v.x), __float2bfloat16(v.y)};
        __nv_bfloat162 h1 = {__float2bfloat16(v.z), __float2bfloat16(v.w)};
        __nv_bfloat162 l0 = {__float2bfloat16(v.x - __bfloat162float(h0.x)),
                             __float2bfloat16(v.y - __bfloat162float(h0.y))};
        __nv_bfloat162 l1 = {__float2bfloat16(v.z - __bfloat162float(h1.x)),
                             __float2bfloat16(v.w - __bfloat162float(h1.y))};
        size_t ob = (base4 + i4) * 2;
        ((__nv_bfloat162*)Oh)[ob]     = h0;
        ((__nv_bfloat162*)Oh)[ob + 1] = h1;
        ((__nv_bfloat162*)Ol)[ob]     = l0;
        ((__nv_bfloat162*)Ol)[ob + 1] = l1;
    }
}

// ---------------- out = LN(A + B) * g + beta (float4) --------------------------
__global__ void __launch_bounds__(256)
add_ln_kernel(const float* __restrict__ A, const float* __restrict__ Bv,
              const float* __restrict__ g, const float* __restrict__ be,
              float* __restrict__ out)
{
    __shared__ float red[16];
    const int t = blockIdx.x, tid = threadIdx.x;
    const size_t base4 = (size_t)t * (DDIM / 4);
    const float4* A4 = (const float4*)A;
    const float4* B4 = (const float4*)Bv;
    float4 xp[2];
    float ls = 0.f, lq = 0.f;
    #pragma unroll
    for (int it = 0; it < 2; it++) {
        int i4 = tid + it * 256;
        float4 a = A4[base4 + i4], b = B4[base4 + i4];
        float4 xv = {a.x + b.x, a.y + b.y, a.z + b.z, a.w + b.w};
        xp[it] = xv;
        ls += xv.x + xv.y + xv.z + xv.w;
        lq += xv.x * xv.x + xv.y * xv.y + xv.z * xv.z + xv.w * xv.w;
    }
    #pragma unroll
    for (int off = 16; off; off >>= 1) {
        ls += __shfl_xor_sync(0xffffffffu, ls, off);
        lq += __shfl_xor_sync(0xffffffffu, lq, off);
    }
    if ((tid & 31) == 0) { red[tid >> 5] = ls; red[8 + (tid >> 5)] = lq; }
    __syncthreads();
    float S = 0.f, Qs = 0.f;
    #pragma unroll
    for (int w = 0; w < 8; w++) { S += red[w]; Qs += red[8 + w]; }
    float mean = S * (1.0f / DDIM);
    float var  = Qs * (1.0f / DDIM) - mean * mean;
    float inv  = rsqrtf(var + 1e-5f);
    const float4* G4 = (const float4*)g;
    const float4* Be4 = (const float4*)be;
    #pragma unroll
    for (int it = 0; it < 2; it++) {
        int i4 = tid + it * 256;
        float4 gg = G4[i4], bb = Be4[i4];
        float4 xv = xp[it];
        float4 v;
        v.x = (xv.x - mean) * inv * gg.x + bb.x;
        v.y = (xv.y - mean) * inv * gg.y + bb.y;
        v.z = (xv.z - mean) * inv * gg.z + bb.z;
        v.w = (xv.w - mean) * inv * gg.w + bb.w;
        ((float4*)out)[base4 + i4] = v;
    }
}

// ---------------- host orchestration -------------------------------------------
extern "C" void kernel_launch(void* const* d_in, const int* in_sizes, int n_in,
                              void* d_out, int out_size)
{
    const float* X     = (const float*)d_in[0];
    const float* Wq    = (const float*)d_in[1];
    const float* bq    = (const float*)d_in[2];
    const float* Wk    = (const float*)d_in[3];
    const float* bk    = (const float*)d_in[4];
    const float* Wv    = (const float*)d_in[5];
    const float* bv    = (const float*)d_in[6];
    const float* g1    = (const float*)d_in[7];
    const float* beta1 = (const float*)d_in[8];
    const float* W1    = (const float*)d_in[9];
    const float* b1    = (const float*)d_in[10];
    const float* W2    = (const float*)d_in[11];
    const float* b2    = (const float*)d_in[12];
    const float* g2    = (const float*)d_in[13];
    const float* beta2 = (const float*)d_in[14];
    float* out = (float*)d_out;

    __nv_bfloat16 *Ah, *Al, *Hh, *Hl, *Wh, *Wl;
    float *Q, *K, *V, *X1;
    cudaGetSymbolAddress((void**)&Ah, g_Ah);
    cudaGetSymbolAddress((void**)&Al, g_Al);
    cudaGetSymbolAddress((void**)&Hh, g_Hh);
    cudaGetSymbolAddress((void**)&Hl, g_Hl);
    cudaGetSymbolAddress((void**)&Wh, g_Wh);
    cudaGetSymbolAddress((void**)&Wl, g_Wl);
    cudaGetSymbolAddress((void**)&Q,  g_Q);
    cudaGetSymbolAddress((void**)&K,  g_K);
    cudaGetSymbolAddress((void**)&V,  g_V);
    cudaGetSymbolAddress((void**)&X1, g_X1);

    cudaFuncSetAttribute(gemm_bf16x3<0>, cudaFuncAttributeMaxDynamicSharedMemorySize, GEMM_SMEM);
    cudaFuncSetAttribute(gemm_bf16x3<1>, cudaFuncAttributeMaxDynamicSharedMemorySize, GEMM_SMEM);

    // launch 0: all splits fused (X + 5 weights)
    {
        int gx = (MROWS * DDIM / 4 + 255) / 256;   // 32768 (covers the largest)
        dim3 gs(gx, 6);
        split_all_kernel<<<gs, 256>>>(X, Wq, Wk, Wv, W1, W2, Ah, Al, Wh, Wl);
    }

    dim3 gg(DDIM / BN, MROWS / BM);   // (8, 128)
    // launches 1..3
    gemm_bf16x3<0><<<gg, 256, GEMM_SMEM>>>(Ah, Al, Wh + 0 * WSZ, Wl + 0 * WSZ, bq, Q,  nullptr, nullptr);
    gemm_bf16x3<0><<<gg, 256, GEMM_SMEM>>>(Ah, Al, Wh + 1 * WSZ, Wl + 1 * WSZ, bk, K,  nullptr, nullptr);
    gemm_bf16x3<0><<<gg, 256, GEMM_SMEM>>>(Ah, Al, Wh + 2 * WSZ, Wl + 2 * WSZ, bv, V,  nullptr, nullptr);
    // launch 4
    attn_ln1_kernel<<<MROWS, 128>>>(Q, K, V, X, g1, beta1, X1, Ah, Al);
    // launch 5  <-- ncu -s 5 -c 1 captures THIS (FFN GEMM + GELU epilogue)
    gemm_bf16x3<1><<<gg, 256, GEMM_SMEM>>>(Ah, Al, Wh + 3 * WSZ, Wl + 3 * WSZ, b1, nullptr, Hh, Hl);
    // launch 6
    gemm_bf16x3<0><<<gg, 256, GEMM_SMEM>>>(Hh, Hl, Wh + 4 * WSZ, Wl + 4 * WSZ, b2, Q,  nullptr, nullptr);
    // launch 7
    add_ln_kernel<<<MROWS, 256>>>(X1, Q, g2, beta2, out);
}

// round 9
// speedup vs baseline: 1.4640x; 1.4640x over previous
#include <cuda_runtime.h>
#include <cuda_bf16.h>
#include <mma.h>
#include <cuda_pipeline.h>
#include <math.h>

using namespace nvcuda;

// Problem dims
#define MROWS 16384            // B*S
#define DDIM  2048             // D
#define MSZ   ((size_t)MROWS * DDIM)
#define WSZ   ((size_t)DDIM * DDIM)

// ---------------- device scratch (allocation-free rule) ------------------------
__device__ __nv_bfloat16 g_Ah[MSZ];
__device__ __nv_bfloat16 g_Al[MSZ];
__device__ __nv_bfloat16 g_Hh[MSZ];
__device__ __nv_bfloat16 g_Hl[MSZ];
__device__ __nv_bfloat16 g_Wh[5 * WSZ];    // weight splits [K,N] row-major
__device__ __nv_bfloat16 g_Wl[5 * WSZ];
__device__ float g_Q [MSZ];
__device__ float g_K [MSZ];
__device__ float g_V [MSZ];
__device__ float g_X1[MSZ];

// ---------------- fused split: X + all 5 weights in ONE launch ------------------
__global__ void __launch_bounds__(256)
split_all_kernel(const float* __restrict__ X,
                 const float* __restrict__ W0, const float* __restrict__ W1,
                 const float* __restrict__ W2, const float* __restrict__ W3,
                 const float* __restrict__ W4,
                 __nv_bfloat16* __restrict__ Ah, __nv_bfloat16* __restrict__ Al,
                 __nv_bfloat16* __restrict__ Wh, __nv_bfloat16* __restrict__ Wl)
{
    const int which = blockIdx.y;
    const float* src;
    __nv_bfloat16 *oh, *ol;
    int n4;
    if (which == 0) {
        src = X; oh = Ah; ol = Al; n4 = (MROWS * DDIM) / 4;
    } else {
        const float* Ws[5] = {W0, W1, W2, W3, W4};
        src = Ws[which - 1];
        oh = Wh + (size_t)(which - 1) * WSZ;
        ol = Wl + (size_t)(which - 1) * WSZ;
        n4 = (DDIM * DDIM) / 4;
    }
    int i = blockIdx.x * 256 + threadIdx.x;
    if (i >= n4) return;
    float4 v = ((const float4*)src)[i];
    __nv_bfloat162 h0 = {__float2bfloat16(v.x), __float2bfloat16(v.y)};
    __nv_bfloat162 h1 = {__float2bfloat16(v.z), __float2bfloat16(v.w)};
    __nv_bfloat162 l0 = {__float2bfloat16(v.x - __bfloat162float(h0.x)),
                         __float2bfloat16(v.y - __bfloat162float(h0.y))};
    __nv_bfloat162 l1 = {__float2bfloat16(v.z - __bfloat162float(h1.x)),
                         __float2bfloat16(v.w - __bfloat162float(h1.y))};
    ((__nv_bfloat162*)oh)[2 * i]     = h0;
    ((__nv_bfloat162*)oh)[2 * i + 1] = h1;
    ((__nv_bfloat162*)ol)[2 * i]     = l0;
    ((__nv_bfloat162*)ol)[2 * i + 1] = l1;
}

// ================= bf16x3 GEMM (HMMA), 16 warps / 64x32 warp tile ==============
// C[M,N] = (Ah+Al)(Bh+Bl), fp32 accum. Logical K3 = 3*2048:
//   seg0 = Ah*Bh, seg1 = Al*Bh, seg2 = Ah*Bl
// CTA 128x256, BK=32, 3-stage cp.async, 512 threads (4 warps/SMSP for latency).
constexpr int BM = 128, BN = 256, BK = 32;
constexpr int NSTG = 3;
constexpr int APAD = 8,  LDA = BK + APAD;     // 40
constexpr int BPAD = 8,  LDB = BN + BPAD;     // 264
constexpr int A_BYTES = BM * LDA * 2;         // 10240
constexpr int B_BYTES = BK * LDB * 2;         // 16896
constexpr int STG_BYTES = A_BYTES + B_BYTES;  // 27136
constexpr int GEMM_SMEM = NSTG * STG_BYTES;   // 81408
constexpr int GT = 512;                        // GEMM threads

template<int EPI>
__global__ void __launch_bounds__(GT, 1)
gemm_bf16x3(const __nv_bfloat16* __restrict__ Ah, const __nv_bfloat16* __restrict__ Al,
            const __nv_bfloat16* __restrict__ Bh, const __nv_bfloat16* __restrict__ Bl,
            const float* __restrict__ bias,
            float* __restrict__ C,
            __nv_bfloat16* __restrict__ Oh, __nv_bfloat16* __restrict__ Ol)
{
    constexpr int K = DDIM, N = DDIM;
    extern __shared__ char dsm[];

    const int tid  = threadIdx.x;
    const int warp = tid >> 5, lane = tid & 31;
    const int wr = warp >> 3;          // 0..1 -> 64-row slab
    const int wc = warp & 7;           // 0..7 -> 32-col slab
    const int m0 = blockIdx.y * BM, n0 = blockIdx.x * BN;

    wmma::fragment<wmma::accumulator, 16, 16, 16, float> acc[4][2];
    #pragma unroll
    for (int i = 0; i < 4; i++)
        #pragma unroll
        for (int j = 0; j < 2; j++) wmma::fill_fragment(acc[i][j], 0.0f);

    auto load_stage = [&](int s, int kt) {
        int seg = (kt >= 2 * K) ? 2 : ((kt >= K) ? 1 : 0);
        int kk  = kt - seg * K;
        const __nv_bfloat16* Ap = (seg == 1) ? Al : Ah;
        const __nv_bfloat16* Bp = (seg == 2) ? Bl : Bh;
        __nv_bfloat16* sA = (__nv_bfloat16*)(dsm + s * STG_BYTES);
        __nv_bfloat16* sB = (__nv_bfloat16*)(dsm + s * STG_BYTES + A_BYTES);
        {   // A: 128x32 = 512 x 16B chunks, one per thread
            int row = tid >> 2, c8 = (tid & 3) * 8;
            __pipeline_memcpy_async(sA + row * LDA + c8,
                                    Ap + (size_t)(m0 + row) * K + kk + c8, 16);
        }
        #pragma unroll
        for (int r = 0; r < 2; r++) {   // B: 32x256 = 1024 x 16B chunks
            int idx = tid + r * GT;
            int row = idx >> 5, c8 = (idx & 31) * 8;
            __pipeline_memcpy_async(sB + row * LDB + c8,
                                    Bp + (size_t)(kk + row) * N + n0 + c8, 16);
        }
    };

    const int nIter = (3 * K) / BK;   // 192
    load_stage(0, 0);             __pipeline_commit();
    load_stage(1, BK);            __pipeline_commit();

    for (int it = 0; it < nIter; ++it) {
        int cur = it % NSTG;
        __pipeline_wait_prior(1);          // stage `it` resident
        __syncthreads();                   // prev compute done before overwrite
        if (it + 2 < nIter) load_stage((it + 2) % NSTG, (it + 2) * BK);
        __pipeline_commit();

        const __nv_bfloat16* sA = (const __nv_bfloat16*)(dsm + cur * STG_BYTES);
        const __nv_bfloat16* sB = (const __nv_bfloat16*)(dsm + cur * STG_BYTES + A_BYTES);
        #pragma unroll
        for (int k2 = 0; k2 < BK; k2 += 16) {
            wmma::fragment<wmma::matrix_a, 16, 16, 16, __nv_bfloat16, wmma::row_major> af[4];
            wmma::fragment<wmma::matrix_b, 16, 16, 16, __nv_bfloat16, wmma::row_major> bf[2];
            #pragma unroll
            for (int i = 0; i < 4; i++)
                wmma::load_matrix_sync(af[i], sA + (wr * 64 + i * 16) * LDA + k2, LDA);
            #pragma unroll
            for (int j = 0; j < 2; j++)
                wmma::load_matrix_sync(bf[j], sB + k2 * LDB + wc * 32 + j * 16, LDB);
            #pragma unroll
            for (int i = 0; i < 4; i++)
                #pragma unroll
                for (int j = 0; j < 2; j++)
                    wmma::mma_sync(acc[i][j], af[i], bf[j], acc[i][j]);
        }
    }
    __syncthreads();

    // epilogue: per-warp smem staging, coalesced stores
    float* buf = (float*)dsm + warp * 272;
    #pragma unroll
    for (int i = 0; i < 4; i++) {
        #pragma unroll
        for (int j = 0; j < 2; j++) {
            wmma::store_matrix_sync(buf, acc[i][j], 16, wmma::mem_row_major);
            __syncwarp();
            const int gr = m0 + wr * 64 + i * 16;
            const int gc = n0 + wc * 32 + j * 16;
            const int r  = lane >> 1, ch = (lane & 1) * 8;
            #pragma unroll
            for (int e = 0; e < 8; e++) {
                int cc = ch + e;
                float v = buf[r * 16 + cc] + bias[gc + cc];
                size_t o = (size_t)(gr + r) * N + gc + cc;
                if (EPI == 0) {
                    C[o] = v;
                } else {
                    float gl = v * normcdff(v);            // exact GELU
                    __nv_bfloat16 hh = __float2bfloat16(gl);
                    Oh[o] = hh;
                    Ol[o] = __float2bfloat16(gl - __bfloat162float(hh));
                }
            }
            __syncwarp();
        }
    }
}

// ---------------- per-token head-attention + residual + LN1 (float4) -----------
__global__ void __launch_bounds__(128)
attn_ln1_kernel(const float* __restrict__ Q, const float* __restrict__ Kk,
                const float* __restrict__ V, const float* __restrict__ X,
                const float* __restrict__ g1, const float* __restrict__ be1,
                float* __restrict__ X1,
                __nv_bfloat16* __restrict__ Oh, __nv_bfloat16* __restrict__ Ol)
{
    __shared__ float sq[16 * 129], sk[16 * 129], sv[16 * 129];
    __shared__ float satt[16][16];
    __shared__ float red[8];
    const int t = blockIdx.x, tid = threadIdx.x;
    const size_t base4 = (size_t)t * (DDIM / 4);

    const float4* Q4 = (const float4*)Q;
    const float4* K4 = (const float4*)Kk;
    const float4* V4 = (const float4*)V;
    const float4* X4 = (const float4*)X;

    #pragma unroll
    for (int it = 0; it < 4; it++) {
        int i4 = tid + it * 128;
        int e = i4 * 4, h = e >> 7, d = e & 127, o = h * 129 + d;
        float4 q = Q4[base4 + i4], k = K4[base4 + i4], v = V4[base4 + i4];
        sq[o] = q.x; sq[o+1] = q.y; sq[o+2] = q.z; sq[o+3] = q.w;
        sk[o] = k.x; sk[o+1] = k.y; sk[o+2] = k.z; sk[o+3] = k.w;
        sv[o] = v.x; sv[o+1] = v.y; sv[o+2] = v.z; sv[o+3] = v.w;
    }
    __syncthreads();

    #pragma unroll
    for (int p = tid; p < 256; p += 128) {
        int h = p >> 4, tt = p & 15;
        const float* qp = sq + h * 129;
        const float* kp = sk + tt * 129;
        float s = 0.f;
        #pragma unroll
        for (int d = 0; d < 128; d++) s += qp[d] * kp[d];
        satt[h][tt] = s * 0.08838834764831845f;     // 1/sqrt(128)
    }
    __syncthreads();

    if (tid < 16) {
        float mx = -1e30f;
        #pragma unroll
        for (int j = 0; j < 16; j++) mx = fmaxf(mx, satt[tid][j]);
        float sum = 0.f;
        #pragma unroll
        for (int j = 0; j < 16; j++) { float e = expf(satt[tid][j] - mx); satt[tid][j] = e; sum += e; }
        float inv = 1.f / sum;
        #pragma unroll
        for (int j = 0; j < 16; j++) satt[tid][j] *= inv;
    }
    __syncthreads();

    float4 xp[4];
    float ls = 0.f, lq = 0.f;
    #pragma unroll
    for (int it = 0; it < 4; it++) {
        int i4 = tid + it * 128;
        int e = i4 * 4, h = e >> 7, d = e & 127;
        float4 xv = X4[base4 + i4];
        float y0 = 0.f, y1 = 0.f, y2 = 0.f, y3 = 0.f;
        #pragma unroll
        for (int tt = 0; tt < 16; tt++) {
            float p = satt[h][tt];
            const float* vp = sv + tt * 129 + d;
            y0 += p * vp[0]; y1 += p * vp[1]; y2 += p * vp[2]; y3 += p * vp[3];
        }
        xv.x += y0; xv.y += y1; xv.z += y2; xv.w += y3;
        xp[it] = xv;
        ls += xv.x + xv.y + xv.z + xv.w;
        lq += xv.x * xv.x + xv.y * xv.y + xv.z * xv.z + xv.w * xv.w;
    }
    #pragma unroll
    for (int off = 16; off; off >>= 1) {
        ls += __shfl_xor_sync(0xffffffffu, ls, off);
        lq += __shfl_xor_sync(0xffffffffu, lq, off);
    }
    if ((tid & 31) == 0) { red[tid >> 5] = ls; red[4 + (tid >> 5)] = lq; }
    __syncthreads();
    float S  = red[0] + red[1] + red[2] + red[3];
    float Qs = red[4] + red[5] + red[6] + red[7];
    float mean = S * (1.0f / DDIM);
    float var  = Qs * (1.0f / DDIM) - mean * mean;
    float inv  = rsqrtf(var + 1e-5f);

    const float4* G4 = (const float4*)g1;
    const float4* Be4 = (const float4*)be1;
    #pragma unroll
    for (int it = 0; it < 4; it++) {
        int i4 = tid + it * 128;
        float4 g = G4[i4], be = Be4[i4];
        float4 xv = xp[it];
        float4 v;
        v.x = (xv.x - mean) * inv * g.x + be.x;
        v.y = (xv.y - mean) * inv * g.y + be.y;
        v.z = (xv.z - mean) * inv * g.z + be.z;
        v.w = (xv.w - mean) * inv * g.w + be.w;
        ((float4*)X1)[base4 + i4] = v;
        __nv_bfloat162 h0 = {__float2bfloat16(v.x), __float2bfloat16(v.y)};
        __nv_bfloat162 h1 = {__float2bfloat16(v.z), __float2bfloat16(v.w)};
        __nv_bfloat162 l0 = {__float2bfloat16(v.x - __bfloat162float(h0.x)),
                             __float2bfloat16(v.y - __bfloat162float(h0.y))};
        __nv_bfloat162 l1 = {__float2bfloat16(v.z - __bfloat162float(h1.x)),
                             __float2bfloat16(v.w - __bfloat162float(h1.y))};
        size_t ob = (base4 + i4) * 2;
        ((__nv_bfloat162*)Oh)[ob]     = h0;
        ((__nv_bfloat162*)Oh)[ob + 1] = h1;
        ((__nv_bfloat162*)Ol)[ob]     = l0;
        ((__nv_bfloat162*)Ol)[ob + 1] = l1;
    }
}

// ---------------- out = LN(A + B) * g + beta (float4) --------------------------
__global__ void __launch_bounds__(256)
add_ln_kernel(const float* __restrict__ A, const float* __restrict__ Bv,
              const float* __restrict__ g, const float* __restrict__ be,
              float* __restrict__ out)
{
    __shared__ float red[16];
    const int t = blockIdx.x, tid = threadIdx.x;
    const size_t base4 = (size_t)t * (DDIM / 4);
    const float4* A4 = (const float4*)A;
    const float4* B4 = (const float4*)Bv;
    float4 xp[2];
    float ls = 0.f, lq = 0.f;
    #pragma unroll
    for (int it = 0; it < 2; it++) {
        int i4 = tid + it * 256;
        float4 a = A4[base4 + i4], b = B4[base4 + i4];
        float4 xv = {a.x + b.x, a.y + b.y, a.z + b.z, a.w + b.w};
        xp[it] = xv;
        ls += xv.x + xv.y + xv.z + xv.w;
        lq += xv.x * xv.x + xv.y * xv.y + xv.z * xv.z + xv.w * xv.w;
    }
    #pragma unroll
    for (int off = 16; off; off >>= 1) {
        ls += __shfl_xor_sync(0xffffffffu, ls, off);
        lq += __shfl_xor_sync(0xffffffffu, lq, off);
    }
    if ((tid & 31) == 0) { red[tid >> 5] = ls; red[8 + (tid >> 5)] = lq; }
    __syncthreads();
    float S = 0.f, Qs = 0.f;
    #pragma unroll
    for (int w = 0; w < 8; w++) { S += red[w]; Qs += red[8 + w]; }
    float mean = S * (1.0f / DDIM);
    float var  = Qs * (1.0f / DDIM) - mean * mean;
    float inv  = rsqrtf(var + 1e-5f);
    const float4* G4 = (const float4*)g;
    const float4* Be4 = (const float4*)be;
    #pragma unroll
    for (int it = 0; it < 2; it++) {
        int i4 = tid + it * 256;
        float4 gg = G4[i4], bb = Be4[i4];
        float4 xv = xp[it];
        float4 v;
        v.x = (xv.x - mean) * inv * gg.x + bb.x;
        v.y = (xv.y - mean) * inv * gg.y + bb.y;
        v.z = (xv.z - mean) * inv * gg.z + bb.z;
        v.w = (xv.w - mean) * inv * gg.w + bb.w;
        ((float4*)out)[base4 + i4] = v;
    }
}

// ---------------- host orchestration -------------------------------------------
extern "C" void kernel_launch(void* const* d_in, const int* in_sizes, int n_in,
                              void* d_out, int out_size)
{
    const float* X     = (const float*)d_in[0];
    const float* Wq    = (const float*)d_in[1];
    const float* bq    = (const float*)d_in[2];
    const float* Wk    = (const float*)d_in[3];
    const float* bk    = (const float*)d_in[4];
    const float* Wv    = (const float*)d_in[5];
    const float* bv    = (const float*)d_in[6];
    const float* g1    = (const float*)d_in[7];
    const float* beta1 = (const float*)d_in[8];
    const float* W1    = (const float*)d_in[9];
    const float* b1    = (const float*)d_in[10];
    const float* W2    = (const float*)d_in[11];
    const float* b2    = (const float*)d_in[12];
    const float* g2    = (const float*)d_in[13];
    const float* beta2 = (const float*)d_in[14];
    float* out = (float*)d_out;

    __nv_bfloat16 *Ah, *Al, *Hh, *Hl, *Wh, *Wl;
    float *Q, *K, *V, *X1;
    cudaGetSymbolAddress((void**)&Ah, g_Ah);
    cudaGetSymbolAddress((void**)&Al, g_Al);
    cudaGetSymbolAddress((void**)&Hh, g_Hh);
    cudaGetSymbolAddress((void**)&Hl, g_Hl);
    cudaGetSymbolAddress((void**)&Wh, g_Wh);
    cudaGetSymbolAddress((void**)&Wl, g_Wl);
    cudaGetSymbolAddress((void**)&Q,  g_Q);
    cudaGetSymbolAddress((void**)&K,  g_K);
    cudaGetSymbolAddress((void**)&V,  g_V);
    cudaGetSymbolAddress((void**)&X1, g_X1);

    cudaFuncSetAttribute(gemm_bf16x3<0>, cudaFuncAttributeMaxDynamicSharedMemorySize, GEMM_SMEM);
    cudaFuncSetAttribute(gemm_bf16x3<1>, cudaFuncAttributeMaxDynamicSharedMemorySize, GEMM_SMEM);

    // launch 0: all splits fused (X + 5 weights)
    {
        int gx = (MROWS * DDIM / 4 + 255) / 256;
        dim3 gs(gx, 6);
        split_all_kernel<<<gs, 256>>>(X, Wq, Wk, Wv, W1, W2, Ah, Al, Wh, Wl);
    }

    dim3 gg(DDIM / BN, MROWS / BM);   // (8, 128)
    // launches 1..3
    gemm_bf16x3<0><<<gg, GT, GEMM_SMEM>>>(Ah, Al, Wh + 0 * WSZ, Wl + 0 * WSZ, bq, Q,  nullptr, nullptr);
    gemm_bf16x3<0><<<gg, GT, GEMM_SMEM>>>(Ah, Al, Wh + 1 * WSZ, Wl + 1 * WSZ, bk, K,  nullptr, nullptr);
    gemm_bf16x3<0><<<gg, GT, GEMM_SMEM>>>(Ah, Al, Wh + 2 * WSZ, Wl + 2 * WSZ, bv, V,  nullptr, nullptr);
    // launch 4
    attn_ln1_kernel<<<MROWS, 128>>>(Q, K, V, X, g1, beta1, X1, Ah, Al);
    // launch 5  <-- ncu -s 5 -c 1 captures THIS (FFN GEMM + GELU epilogue)
    gemm_bf16x3<1><<<gg, GT, GEMM_SMEM>>>(Ah, Al, Wh + 3 * WSZ, Wl + 3 * WSZ, b1, nullptr, Hh, Hl);
    // launch 6
    gemm_bf16x3<0><<<gg, GT, GEMM_SMEM>>>(Hh, Hl, Wh + 4 * WSZ, Wl + 4 * WSZ, b2, Q,  nullptr, nullptr);
    // launch 7
    add_ln_kernel<<<MROWS, 256>>>(X1, Q, g2, beta2, out);
}

// round 10
// speedup vs baseline: 2.6094x; 1.7824x over previous
#include <cuda_runtime.h>
#include <cuda_fp16.h>
#include <mma.h>
#include <cuda_pipeline.h>
#include <math.h>

using namespace nvcuda;

// Problem dims
#define MROWS 16384            // B*S
#define DDIM  2048             // D
#define MSZ   ((size_t)MROWS * DDIM)
#define WSZ   ((size_t)DDIM * DDIM)

// ---------------- device scratch (allocation-free rule) ------------------------
__device__ __half g_Ah[MSZ];               // activation split hi (X, then H)
__device__ __half g_Al[MSZ];               // activation split lo
__device__ __half g_Hh[MSZ];
__device__ __half g_Hl[MSZ];
__device__ __half g_Wf[5 * WSZ];           // weights single fp16 [K,N] row-major
__device__ float g_Q [MSZ];
__device__ float g_K [MSZ];
__device__ float g_V [MSZ];
__device__ float g_X1[MSZ];

// ---------------- fused split/convert: X (2-way) + 5 weights (round) -----------
__global__ void __launch_bounds__(256)
split_all_kernel(const float* __restrict__ X,
                 const float* __restrict__ W0, const float* __restrict__ W1,
                 const float* __restrict__ W2, const float* __restrict__ W3,
                 const float* __restrict__ W4,
                 __half* __restrict__ Ah, __half* __restrict__ Al,
                 __half* __restrict__ Wf)
{
    const int which = blockIdx.y;
    int i = blockIdx.x * 256 + threadIdx.x;
    if (which == 0) {
        int n4 = (MROWS * DDIM) / 4;
        if (i >= n4) return;
        float4 v = ((const float4*)X)[i];
        __half2 h0 = {__float2half(v.x), __float2half(v.y)};
        __half2 h1 = {__float2half(v.z), __float2half(v.w)};
        __half2 l0 = {__float2half(v.x - __half2float(h0.x)),
                      __float2half(v.y - __half2float(h0.y))};
        __half2 l1 = {__float2half(v.z - __half2float(h1.x)),
                      __float2half(v.w - __half2float(h1.y))};
        ((__half2*)Ah)[2 * i]     = h0;
        ((__half2*)Ah)[2 * i + 1] = h1;
        ((__half2*)Al)[2 * i]     = l0;
        ((__half2*)Al)[2 * i + 1] = l1;
    } else {
        const float* Ws[5] = {W0, W1, W2, W3, W4};
        const float* src = Ws[which - 1];
        __half* oh = Wf + (size_t)(which - 1) * WSZ;
        int n4 = (DDIM * DDIM) / 4;
        if (i >= n4) return;
        float4 v = ((const float4*)src)[i];
        __half2 h0 = {__float2half(v.x), __float2half(v.y)};
        __half2 h1 = {__float2half(v.z), __float2half(v.w)};
        ((__half2*)oh)[2 * i]     = h0;
        ((__half2*)oh)[2 * i + 1] = h1;
    }
}

// ================= fp16x2 GEMM (HMMA): C = (Ah+Al) x Bf16, fp32 accum ==========
// Logical K2 = 2*2048: seg0 = Ah*B, seg1 = Al*B.
// CTA 128x256, BK=32, 3-stage cp.async, 8 warps of 64x64 (R7's best shape).
constexpr int BM = 128, BN = 256, BK = 32;
constexpr int NSTG = 3;
constexpr int APAD = 8,  LDA = BK + APAD;     // 40
constexpr int BPAD = 8,  LDB = BN + BPAD;     // 264
constexpr int A_BYTES = BM * LDA * 2;         // 10240
constexpr int B_BYTES = BK * LDB * 2;         // 16896
constexpr int STG_BYTES = A_BYTES + B_BYTES;  // 27136
constexpr int GEMM_SMEM = NSTG * STG_BYTES;   // 81408

template<int EPI>
__global__ void __launch_bounds__(256, 1)
gemm_fp16x2(const __half* __restrict__ Ah, const __half* __restrict__ Al,
            const __half* __restrict__ Bf,
            const float* __restrict__ bias,
            float* __restrict__ C,
            __half* __restrict__ Oh, __half* __restrict__ Ol)
{
    constexpr int K = DDIM, N = DDIM;
    extern __shared__ char dsm[];

    const int tid  = threadIdx.x;
    const int warp = tid >> 5, lane = tid & 31;
    const int wr = warp >> 2;          // 0..1 -> 64-row slab
    const int wc = warp & 3;           // 0..3 -> 64-col slab
    const int m0 = blockIdx.y * BM, n0 = blockIdx.x * BN;

    wmma::fragment<wmma::accumulator, 16, 16, 16, float> acc[4][4];
    #pragma unroll
    for (int i = 0; i < 4; i++)
        #pragma unroll
        for (int j = 0; j < 4; j++) wmma::fill_fragment(acc[i][j], 0.0f);

    auto load_stage = [&](int s, int kt) {
        int seg = (kt >= K) ? 1 : 0;
        int kk  = kt - seg * K;
        const __half* Ap = seg ? Al : Ah;
        __half* sA = (__half*)(dsm + s * STG_BYTES);
        __half* sB = (__half*)(dsm + s * STG_BYTES + A_BYTES);
        #pragma unroll
        for (int r = 0; r < 2; r++) {              // A: 128x32 = 512 x 16B
            int idx = tid + r * 256;
            int row = idx >> 2, c8 = (idx & 3) * 8;
            __pipeline_memcpy_async(sA + row * LDA + c8,
                                    Ap + (size_t)(m0 + row) * K + kk + c8, 16);
        }
        #pragma unroll
        for (int r = 0; r < 4; r++) {              // B: 32x256 = 1024 x 16B
            int idx = tid + r * 256;
            int row = idx >> 5, c8 = (idx & 31) * 8;
            __pipeline_memcpy_async(sB + row * LDB + c8,
                                    Bf + (size_t)(kk + row) * N + n0 + c8, 16);
        }
    };

    const int nIter = (2 * K) / BK;   // 128
    load_stage(0, 0);             __pipeline_commit();
    load_stage(1, BK);            __pipeline_commit();

    for (int it = 0; it < nIter; ++it) {
        int cur = it % NSTG;
        __pipeline_wait_prior(1);          // stage `it` resident
        __syncthreads();                   // prev compute done before overwrite
        if (it + 2 < nIter) load_stage((it + 2) % NSTG, (it + 2) * BK);
        __pipeline_commit();

        const __half* sA = (const __half*)(dsm + cur * STG_BYTES);
        const __half* sB = (const __half*)(dsm + cur * STG_BYTES + A_BYTES);
        #pragma unroll
        for (int k2 = 0; k2 < BK; k2 += 16) {
            wmma::fragment<wmma::matrix_a, 16, 16, 16, __half, wmma::row_major> af[4];
            wmma::fragment<wmma::matrix_b, 16, 16, 16, __half, wmma::row_major> bf[4];
            #pragma unroll
            for (int i = 0; i < 4; i++)
                wmma::load_matrix_sync(af[i], sA + (wr * 64 + i * 16) * LDA + k2, LDA);
            #pragma unroll
            for (int j = 0; j < 4; j++)
                wmma::load_matrix_sync(bf[j], sB + k2 * LDB + wc * 64 + j * 16, LDB);
            #pragma unroll
            for (int i = 0; i < 4; i++)
                #pragma unroll
                for (int j = 0; j < 4; j++)
                    wmma::mma_sync(acc[i][j], af[i], bf[j], acc[i][j]);
        }
    }
    __syncthreads();

    // epilogue: per-warp smem staging, coalesced stores
    float* buf = (float*)dsm + warp * 272;
    #pragma unroll
    for (int i = 0; i < 4; i++) {
        #pragma unroll
        for (int j = 0; j < 4; j++) {
            wmma::store_matrix_sync(buf, acc[i][j], 16, wmma::mem_row_major);
            __syncwarp();
            const int gr = m0 + wr * 64 + i * 16;
            const int gc = n0 + wc * 64 + j * 16;
            const int r  = lane >> 1, ch = (lane & 1) * 8;
            #pragma unroll
            for (int e = 0; e < 8; e++) {
                int cc = ch + e;
                float v = buf[r * 16 + cc] + bias[gc + cc];
                size_t o = (size_t)(gr + r) * N + gc + cc;
                if (EPI == 0) {
                    C[o] = v;
                } else {
                    float gl = v * normcdff(v);            // exact GELU
                    __half hh = __float2half(gl);
                    Oh[o] = hh;
                    Ol[o] = __float2half(gl - __half2float(hh));
                }
            }
            __syncwarp();
        }
    }
}

// ---------------- per-token head-attention + residual + LN1 (float4) -----------
__global__ void __launch_bounds__(128)
attn_ln1_kernel(const float* __restrict__ Q, const float* __restrict__ Kk,
                const float* __restrict__ V, const float* __restrict__ X,
                const float* __restrict__ g1, const float* __restrict__ be1,
                float* __restrict__ X1,
                __half* __restrict__ Oh, __half* __restrict__ Ol)
{
    __shared__ float sq[16 * 129], sk[16 * 129], sv[16 * 129];
    __shared__ float satt[16][16];
    __shared__ float red[8];
    const int t = blockIdx.x, tid = threadIdx.x;
    const size_t base4 = (size_t)t * (DDIM / 4);

    const float4* Q4 = (const float4*)Q;
    const float4* K4 = (const float4*)Kk;
    const float4* V4 = (const float4*)V;
    const float4* X4 = (const float4*)X;

    #pragma unroll
    for (int it = 0; it < 4; it++) {
        int i4 = tid + it * 128;
        int e = i4 * 4, h = e >> 7, d = e & 127, o = h * 129 + d;
        float4 q = Q4[base4 + i4], k = K4[base4 + i4], v = V4[base4 + i4];
        sq[o] = q.x; sq[o+1] = q.y; sq[o+2] = q.z; sq[o+3] = q.w;
        sk[o] = k.x; sk[o+1] = k.y; sk[o+2] = k.z; sk[o+3] = k.w;
        sv[o] = v.x; sv[o+1] = v.y; sv[o+2] = v.z; sv[o+3] = v.w;
    }
    __syncthreads();

    #pragma unroll
    for (int p = tid; p < 256; p += 128) {
        int h = p >> 4, tt = p & 15;
        const float* qp = sq + h * 129;
        const float* kp = sk + tt * 129;
        float s = 0.f;
        #pragma unroll
        for (int d = 0; d < 128; d++) s += qp[d] * kp[d];
        satt[h][tt] = s * 0.08838834764831845f;     // 1/sqrt(128)
    }
    __syncthreads();

    if (tid < 16) {
        float mx = -1e30f;
        #pragma unroll
        for (int j = 0; j < 16; j++) mx = fmaxf(mx, satt[tid][j]);
        float sum = 0.f;
        #pragma unroll
        for (int j = 0; j < 16; j++) { float e = expf(satt[tid][j] - mx); satt[tid][j] = e; sum += e; }
        float inv = 1.f / sum;
        #pragma unroll
        for (int j = 0; j < 16; j++) satt[tid][j] *= inv;
    }
    __syncthreads();

    float4 xp[4];
    float ls = 0.f, lq = 0.f;
    #pragma unroll
    for (int it = 0; it < 4; it++) {
        int i4 = tid + it * 128;
        int e = i4 * 4, h = e >> 7, d = e & 127;
        float4 xv = X4[base4 + i4];
        float y0 = 0.f, y1 = 0.f, y2 = 0.f, y3 = 0.f;
        #pragma unroll
        for (int tt = 0; tt < 16; tt++) {
            float p = satt[h][tt];
            const float* vp = sv + tt * 129 + d;
            y0 += p * vp[0]; y1 += p * vp[1]; y2 += p * vp[2]; y3 += p * vp[3];
        }
        xv.x += y0; xv.y += y1; xv.z += y2; xv.w += y3;
        xp[it] = xv;
        ls += xv.x + xv.y + xv.z + xv.w;
        lq += xv.x * xv.x + xv.y * xv.y + xv.z * xv.z + xv.w * xv.w;
    }
    #pragma unroll
    for (int off = 16; off; off >>= 1) {
        ls += __shfl_xor_sync(0xffffffffu, ls, off);
        lq += __shfl_xor_sync(0xffffffffu, lq, off);
    }
    if ((tid & 31) == 0) { red[tid >> 5] = ls; red[4 + (tid >> 5)] = lq; }
    __syncthreads();
    float S  = red[0] + red[1] + red[2] + red[3];
    float Qs = red[4] + red[5] + red[6] + red[7];
    float mean = S * (1.0f / DDIM);
    float var  = Qs * (1.0f / DDIM) - mean * mean;
    float inv  = rsqrtf(var + 1e-5f);

    const float4* G4 = (const float4*)g1;
    const float4* Be4 = (const float4*)be1;
    #pragma unroll
    for (int it = 0; it < 4; it++) {
        int i4 = tid + it * 128;
        float4 g = G4[i4], be = Be4[i4];
        float4 xv = xp[it];
        float4 v;
        v.x = (xv.x - mean) * inv * g.x + be.x;
        v.y = (xv.y - mean) * inv * g.y + be.y;
        v.z = (xv.z - mean) * inv * g.z + be.z;
        v.w = (xv.w - mean) * inv * g.w + be.w;
        ((float4*)X1)[base4 + i4] = v;
        __half2 h0 = {__float2half(v.x), __float2half(v.y)};
        __half2 h1 = {__float2half(v.z), __float2half(v.w)};
        __half2 l0 = {__float2half(v.x - __half2float(h0.x)),
                      __float2half(v.y - __half2float(h0.y))};
        __half2 l1 = {__float2half(v.z - __half2float(h1.x)),
                      __float2half(v.w - __half2float(h1.y))};
        size_t ob = (base4 + i4) * 2;
        ((__half2*)Oh)[ob]     = h0;
        ((__half2*)Oh)[ob + 1] = h1;
        ((__half2*)Ol)[ob]     = l0;
        ((__half2*)Ol)[ob + 1] = l1;
    }
}

// ---------------- out = LN(A + B) * g + beta (float4) --------------------------
__global__ void __launch_bounds__(256)
add_ln_kernel(const float* __restrict__ A, const float* __restrict__ Bv,
              const float* __restrict__ g, const float* __restrict__ be,
              float* __restrict__ out)
{
    __shared__ float red[16];
    const int t = blockIdx.x, tid = threadIdx.x;
    const size_t base4 = (size_t)t * (DDIM / 4);
    const float4* A4 = (const float4*)A;
    const float4* B4 = (const float4*)Bv;
    float4 xp[2];
    float ls = 0.f, lq = 0.f;
    #pragma unroll
    for (int it = 0; it < 2; it++) {
        int i4 = tid + it * 256;
        float4 a = A4[base4 + i4], b = B4[base4 + i4];
        float4 xv = {a.x + b.x, a.y + b.y, a.z + b.z, a.w + b.w};
        xp[it] = xv;
        ls += xv.x + xv.y + xv.z + xv.w;
        lq += xv.x * xv.x + xv.y * xv.y + xv.z * xv.z + xv.w * xv.w;
    }
    #pragma unroll
    for (int off = 16; off; off >>= 1) {
        ls += __shfl_xor_sync(0xffffffffu, ls, off);
        lq += __shfl_xor_sync(0xffffffffu, lq, off);
    }
    if ((tid & 31) == 0) { red[tid >> 5] = ls; red[8 + (tid >> 5)] = lq; }
    __syncthreads();
    float S = 0.f, Qs = 0.f;
    #pragma unroll
    for (int w = 0; w < 8; w++) { S += red[w]; Qs += red[8 + w]; }
    float mean = S * (1.0f / DDIM);
    float var  = Qs * (1.0f / DDIM) - mean * mean;
    float inv  = rsqrtf(var + 1e-5f);
    const float4* G4 = (const float4*)g;
    const float4* Be4 = (const float4*)be;
    #pragma unroll
    for (int it = 0; it < 2; it++) {
        int i4 = tid + it * 256;
        float4 gg = G4[i4], bb = Be4[i4];
        float4 xv = xp[it];
        float4 v;
        v.x = (xv.x - mean) * inv * gg.x + bb.x;
        v.y = (xv.y - mean) * inv * gg.y + bb.y;
        v.z = (xv.z - mean) * inv * gg.z + bb.z;
        v.w = (xv.w - mean) * inv * gg.w + bb.w;
        ((float4*)out)[base4 + i4] = v;
    }
}

// ---------------- host orchestration -------------------------------------------
extern "C" void kernel_launch(void* const* d_in, const int* in_sizes, int n_in,
                              void* d_out, int out_size)
{
    const float* X     = (const float*)d_in[0];
    const float* Wq    = (const float*)d_in[1];
    const float* bq    = (const float*)d_in[2];
    const float* Wk    = (const float*)d_in[3];
    const float* bk    = (const float*)d_in[4];
    const float* Wv    = (const float*)d_in[5];
    const float* bv    = (const float*)d_in[6];
    const float* g1    = (const float*)d_in[7];
    const float* beta1 = (const float*)d_in[8];
    const float* W1    = (const float*)d_in[9];
    const float* b1    = (const float*)d_in[10];
    const float* W2    = (const float*)d_in[11];
    const float* b2    = (const float*)d_in[12];
    const float* g2    = (const float*)d_in[13];
    const float* beta2 = (const float*)d_in[14];
    float* out = (float*)d_out;

    __half *Ah, *Al, *Hh, *Hl, *Wf;
    float *Q, *K, *V, *X1;
    cudaGetSymbolAddress((void**)&Ah, g_Ah);
    cudaGetSymbolAddress((void**)&Al, g_Al);
    cudaGetSymbolAddress((void**)&Hh, g_Hh);
    cudaGetSymbolAddress((void**)&Hl, g_Hl);
    cudaGetSymbolAddress((void**)&Wf, g_Wf);
    cudaGetSymbolAddress((void**)&Q,  g_Q);
    cudaGetSymbolAddress((void**)&K,  g_K);
    cudaGetSymbolAddress((void**)&V,  g_V);
    cudaGetSymbolAddress((void**)&X1, g_X1);

    cudaFuncSetAttribute(gemm_fp16x2<0>, cudaFuncAttributeMaxDynamicSharedMemorySize, GEMM_SMEM);
    cudaFuncSetAttribute(gemm_fp16x2<1>, cudaFuncAttributeMaxDynamicSharedMemorySize, GEMM_SMEM);

    // launch 0: all splits/converts fused (X 2-way + 5 weights rounded)
    {
        int gx = (MROWS * DDIM / 4 + 255) / 256;
        dim3 gs(gx, 6);
        split_all_kernel<<<gs, 256>>>(X, Wq, Wk, Wv, W1, W2, Ah, Al, Wf);
    }

    dim3 gg(DDIM / BN, MROWS / BM);   // (8, 128)
    // launches 1..3
    gemm_fp16x2<0><<<gg, 256, GEMM_SMEM>>>(Ah, Al, Wf + 0 * WSZ, bq, Q,  nullptr, nullptr);
    gemm_fp16x2<0><<<gg, 256, GEMM_SMEM>>>(Ah, Al, Wf + 1 * WSZ, bk, K,  nullptr, nullptr);
    gemm_fp16x2<0><<<gg, 256, GEMM_SMEM>>>(Ah, Al, Wf + 2 * WSZ, bv, V,  nullptr, nullptr);
    // launch 4
    attn_ln1_kernel<<<MROWS, 128>>>(Q, K, V, X, g1, beta1, X1, Ah, Al);
    // launch 5  <-- ncu -s 5 -c 1 captures THIS (FFN GEMM + GELU epilogue)
    gemm_fp16x2<1><<<gg, 256, GEMM_SMEM>>>(Ah, Al, Wf + 3 * WSZ, b1, nullptr, Hh, Hl);
    // launch 6
    gemm_fp16x2<0><<<gg, 256, GEMM_SMEM>>>(Hh, Hl, Wf + 4 * WSZ, b2, Q,  nullptr, nullptr);
    // launch 7
    add_ln_kernel<<<MROWS, 256>>>(X1, Q, g2, beta2, out);
}

// round 11
// speedup vs baseline: 2.8783x; 1.1030x over previous
#include <cuda_runtime.h>
#include <cuda_fp16.h>
#include <mma.h>
#include <cuda_pipeline.h>
#include <math.h>

using namespace nvcuda;

// Problem dims
#define MROWS 16384            // B*S
#define DDIM  2048             // D
#define MSZ   ((size_t)MROWS * DDIM)
#define WSZ   ((size_t)DDIM * DDIM)

// ---------------- device scratch (allocation-free rule) ------------------------
__device__ __half g_Ah[MSZ];               // activation split hi (X, then H)
__device__ __half g_Al[MSZ];               // activation split lo
__device__ __half g_Hh[MSZ];
__device__ __half g_Hl[MSZ];
__device__ __half g_Wf[5 * WSZ];           // weights single fp16 [K,N] row-major
__device__ float g_Q [MSZ];
__device__ float g_K [MSZ];
__device__ float g_V [MSZ];
__device__ float g_X1[MSZ];

// ---------------- fused split/convert: X (2-way) + 5 weights (round) -----------
__global__ void __launch_bounds__(256)
split_all_kernel(const float* __restrict__ X,
                 const float* __restrict__ W0, const float* __restrict__ W1,
                 const float* __restrict__ W2, const float* __restrict__ W3,
                 const float* __restrict__ W4,
                 __half* __restrict__ Ah, __half* __restrict__ Al,
                 __half* __restrict__ Wf)
{
    const int which = blockIdx.y;
    int i = blockIdx.x * 256 + threadIdx.x;
    if (which == 0) {
        int n4 = (MROWS * DDIM) / 4;
        if (i >= n4) return;
        float4 v = ((const float4*)X)[i];
        __half2 h0 = {__float2half(v.x), __float2half(v.y)};
        __half2 h1 = {__float2half(v.z), __float2half(v.w)};
        __half2 l0 = {__float2half(v.x - __half2float(h0.x)),
                      __float2half(v.y - __half2float(h0.y))};
        __half2 l1 = {__float2half(v.z - __half2float(h1.x)),
                      __float2half(v.w - __half2float(h1.y))};
        ((__half2*)Ah)[2 * i]     = h0;
        ((__half2*)Ah)[2 * i + 1] = h1;
        ((__half2*)Al)[2 * i]     = l0;
        ((__half2*)Al)[2 * i + 1] = l1;
    } else {
        const float* Ws[5] = {W0, W1, W2, W3, W4};
        const float* src = Ws[which - 1];
        __half* oh = Wf + (size_t)(which - 1) * WSZ;
        int n4 = (DDIM * DDIM) / 4;
        if (i >= n4) return;
        float4 v = ((const float4*)src)[i];
        __half2 h0 = {__float2half(v.x), __float2half(v.y)};
        __half2 h1 = {__float2half(v.z), __float2half(v.w)};
        ((__half2*)oh)[2 * i]     = h0;
        ((__half2*)oh)[2 * i + 1] = h1;
    }
}

// ================= fp16x2 GEMM (HMMA): C = (Ah+Al) x Bf16, fp32 accum ==========
// Logical K2 = 2*2048: seg0 = Ah*B, seg1 = Al*B.
// CTA 128x128, BK=32, 3-stage cp.async, 8 warps of 64x32, 2 CTAs/SM so one
// CTA's HMMA stream covers the other's barrier/pipeline-wait bubbles.
constexpr int BM = 128, BN = 128, BK = 32;
constexpr int NSTG = 3;
constexpr int APAD = 8,  LDA = BK + APAD;     // 40
constexpr int BPAD = 8,  LDB = BN + BPAD;     // 136
constexpr int A_BYTES = BM * LDA * 2;         // 10240
constexpr int B_BYTES = BK * LDB * 2;         // 8704
constexpr int STG_BYTES = A_BYTES + B_BYTES;  // 18944
constexpr int GEMM_SMEM = NSTG * STG_BYTES;   // 56832  (x2 CTAs = 113664 < 227KB)

template<int EPI>
__global__ void __launch_bounds__(256, 2)
gemm_fp16x2(const __half* __restrict__ Ah, const __half* __restrict__ Al,
            const __half* __restrict__ Bf,
            const float* __restrict__ bias,
            float* __restrict__ C,
            __half* __restrict__ Oh, __half* __restrict__ Ol)
{
    constexpr int K = DDIM, N = DDIM;
    extern __shared__ char dsm[];

    const int tid  = threadIdx.x;
    const int warp = tid >> 5, lane = tid & 31;
    const int wr = warp >> 2;          // 0..1 -> 64-row slab
    const int wc = warp & 3;           // 0..3 -> 32-col slab
    const int m0 = blockIdx.y * BM, n0 = blockIdx.x * BN;

    wmma::fragment<wmma::accumulator, 16, 16, 16, float> acc[4][2];
    #pragma unroll
    for (int i = 0; i < 4; i++)
        #pragma unroll
        for (int j = 0; j < 2; j++) wmma::fill_fragment(acc[i][j], 0.0f);

    auto load_stage = [&](int s, int kt) {
        int seg = (kt >= K) ? 1 : 0;
        int kk  = kt - seg * K;
        const __half* Ap = seg ? Al : Ah;
        __half* sA = (__half*)(dsm + s * STG_BYTES);
        __half* sB = (__half*)(dsm + s * STG_BYTES + A_BYTES);
        #pragma unroll
        for (int r = 0; r < 2; r++) {              // A: 128x32 = 512 x 16B
            int idx = tid + r * 256;
            int row = idx >> 2, c8 = (idx & 3) * 8;
            __pipeline_memcpy_async(sA + row * LDA + c8,
                                    Ap + (size_t)(m0 + row) * K + kk + c8, 16);
        }
        #pragma unroll
        for (int r = 0; r < 2; r++) {              // B: 32x128 = 512 x 16B
            int idx = tid + r * 256;
            int row = idx >> 4, c8 = (idx & 15) * 8;
            __pipeline_memcpy_async(sB + row * LDB + c8,
                                    Bf + (size_t)(kk + row) * N + n0 + c8, 16);
        }
    };

    const int nIter = (2 * K) / BK;   // 128
    load_stage(0, 0);             __pipeline_commit();
    load_stage(1, BK);            __pipeline_commit();

    for (int it = 0; it < nIter; ++it) {
        int cur = it % NSTG;
        __pipeline_wait_prior(1);          // stage `it` resident
        __syncthreads();                   // prev compute done before overwrite
        if (it + 2 < nIter) load_stage((it + 2) % NSTG, (it + 2) * BK);
        __pipeline_commit();

        const __half* sA = (const __half*)(dsm + cur * STG_BYTES);
        const __half* sB = (const __half*)(dsm + cur * STG_BYTES + A_BYTES);
        #pragma unroll
        for (int k2 = 0; k2 < BK; k2 += 16) {
            wmma::fragment<wmma::matrix_a, 16, 16, 16, __half, wmma::row_major> af[4];
            wmma::fragment<wmma::matrix_b, 16, 16, 16, __half, wmma::row_major> bf[2];
            #pragma unroll
            for (int i = 0; i < 4; i++)
                wmma::load_matrix_sync(af[i], sA + (wr * 64 + i * 16) * LDA + k2, LDA);
            #pragma unroll
            for (int j = 0; j < 2; j++)
                wmma::load_matrix_sync(bf[j], sB + k2 * LDB + wc * 32 + j * 16, LDB);
            #pragma unroll
            for (int i = 0; i < 4; i++)
                #pragma unroll
                for (int j = 0; j < 2; j++)
                    wmma::mma_sync(acc[i][j], af[i], bf[j], acc[i][j]);
        }
    }
    __syncthreads();

    // epilogue: per-warp smem staging, coalesced stores
    float* buf = (float*)dsm + warp * 272;
    #pragma unroll
    for (int i = 0; i < 4; i++) {
        #pragma unroll
        for (int j = 0; j < 2; j++) {
            wmma::store_matrix_sync(buf, acc[i][j], 16, wmma::mem_row_major);
            __syncwarp();
            const int gr = m0 + wr * 64 + i * 16;
            const int gc = n0 + wc * 32 + j * 16;
            const int r  = lane >> 1, ch = (lane & 1) * 8;
            #pragma unroll
            for (int e = 0; e < 8; e++) {
                int cc = ch + e;
                float v = buf[r * 16 + cc] + bias[gc + cc];
                size_t o = (size_t)(gr + r) * N + gc + cc;
                if (EPI == 0) {
                    C[o] = v;
                } else {
                    float gl = v * normcdff(v);            // exact GELU
                    __half hh = __float2half(gl);
                    Oh[o] = hh;
                    Ol[o] = __float2half(gl - __half2float(hh));
                }
            }
            __syncwarp();
        }
    }
}

// ---------------- per-token head-attention + residual + LN1 (float4) -----------
__global__ void __launch_bounds__(128)
attn_ln1_kernel(const float* __restrict__ Q, const float* __restrict__ Kk,
                const float* __restrict__ V, const float* __restrict__ X,
                const float* __restrict__ g1, const float* __restrict__ be1,
                float* __restrict__ X1,
                __half* __restrict__ Oh, __half* __restrict__ Ol)
{
    __shared__ float sq[16 * 129], sk[16 * 129], sv[16 * 129];
    __shared__ float satt[16][16];
    __shared__ float red[8];
    const int t = blockIdx.x, tid = threadIdx.x;
    const size_t base4 = (size_t)t * (DDIM / 4);

    const float4* Q4 = (const float4*)Q;
    const float4* K4 = (const float4*)Kk;
    const float4* V4 = (const float4*)V;
    const float4* X4 = (const float4*)X;

    #pragma unroll
    for (int it = 0; it < 4; it++) {
        int i4 = tid + it * 128;
        int e = i4 * 4, h = e >> 7, d = e & 127, o = h * 129 + d;
        float4 q = Q4[base4 + i4], k = K4[base4 + i4], v = V4[base4 + i4];
        sq[o] = q.x; sq[o+1] = q.y; sq[o+2] = q.z; sq[o+3] = q.w;
        sk[o] = k.x; sk[o+1] = k.y; sk[o+2] = k.z; sk[o+3] = k.w;
        sv[o] = v.x; sv[o+1] = v.y; sv[o+2] = v.z; sv[o+3] = v.w;
    }
    __syncthreads();

    #pragma unroll
    for (int p = tid; p < 256; p += 128) {
        int h = p >> 4, tt = p & 15;
        const float* qp = sq + h * 129;
        const float* kp = sk + tt * 129;
        float s = 0.f;
        #pragma unroll
        for (int d = 0; d < 128; d++) s += qp[d] * kp[d];
        satt[h][tt] = s * 0.08838834764831845f;     // 1/sqrt(128)
    }
    __syncthreads();

    if (tid < 16) {
        float mx = -1e30f;
        #pragma unroll
        for (int j = 0; j < 16; j++) mx = fmaxf(mx, satt[tid][j]);
        float sum = 0.f;
        #pragma unroll
        for (int j = 0; j < 16; j++) { float e = expf(satt[tid][j] - mx); satt[tid][j] = e; sum += e; }
        float inv = 1.f / sum;
        #pragma unroll
        for (int j = 0; j < 16; j++) satt[tid][j] *= inv;
    }
    __syncthreads();

    float4 xp[4];
    float ls = 0.f, lq = 0.f;
    #pragma unroll
    for (int it = 0; it < 4; it++) {
        int i4 = tid + it * 128;
        int e = i4 * 4, h = e >> 7, d = e & 127;
        float4 xv = X4[base4 + i4];
        float y0 = 0.f, y1 = 0.f, y2 = 0.f, y3 = 0.f;
        #pragma unroll
        for (int tt = 0; tt < 16; tt++) {
            float p = satt[h][tt];
            const float* vp = sv + tt * 129 + d;
            y0 += p * vp[0]; y1 += p * vp[1]; y2 += p * vp[2]; y3 += p * vp[3];
        }
        xv.x += y0; xv.y += y1; xv.z += y2; xv.w += y3;
        xp[it] = xv;
        ls += xv.x + xv.y + xv.z + xv.w;
        lq += xv.x * xv.x + xv.y * xv.y + xv.z * xv.z + xv.w * xv.w;
    }
    #pragma unroll
    for (int off = 16; off; off >>= 1) {
        ls += __shfl_xor_sync(0xffffffffu, ls, off);
        lq += __shfl_xor_sync(0xffffffffu, lq, off);
    }
    if ((tid & 31) == 0) { red[tid >> 5] = ls; red[4 + (tid >> 5)] = lq; }
    __syncthreads();
    float S  = red[0] + red[1] + red[2] + red[3];
    float Qs = red[4] + red[5] + red[6] + red[7];
    float mean = S * (1.0f / DDIM);
    float var  = Qs * (1.0f / DDIM) - mean * mean;
    float inv  = rsqrtf(var + 1e-5f);

    const float4* G4 = (const float4*)g1;
    const float4* Be4 = (const float4*)be1;
    #pragma unroll
    for (int it = 0; it < 4; it++) {
        int i4 = tid + it * 128;
        float4 g = G4[i4], be = Be4[i4];
        float4 xv = xp[it];
        float4 v;
        v.x = (xv.x - mean) * inv * g.x + be.x;
        v.y = (xv.y - mean) * inv * g.y + be.y;
        v.z = (xv.z - mean) * inv * g.z + be.z;
        v.w = (xv.w - mean) * inv * g.w + be.w;
        ((float4*)X1)[base4 + i4] = v;
        __half2 h0 = {__float2half(v.x), __float2half(v.y)};
        __half2 h1 = {__float2half(v.z), __float2half(v.w)};
        __half2 l0 = {__float2half(v.x - __half2float(h0.x)),
                      __float2half(v.y - __half2float(h0.y))};
        __half2 l1 = {__float2half(v.z - __half2float(h1.x)),
                      __float2half(v.w - __half2float(h1.y))};
        size_t ob = (base4 + i4) * 2;
        ((__half2*)Oh)[ob]     = h0;
        ((__half2*)Oh)[ob + 1] = h1;
        ((__half2*)Ol)[ob]     = l0;
        ((__half2*)Ol)[ob + 1] = l1;
    }
}

// ---------------- out = LN(A + B) * g + beta (float4) --------------------------
__global__ void __launch_bounds__(256)
add_ln_kernel(const float* __restrict__ A, const float* __restrict__ Bv,
              const float* __restrict__ g, const float* __restrict__ be,
              float* __restrict__ out)
{
    __shared__ float red[16];
    const int t = blockIdx.x, tid = threadIdx.x;
    const size_t base4 = (size_t)t * (DDIM / 4);
    const float4* A4 = (const float4*)A;
    const float4* B4 = (const float4*)Bv;
    float4 xp[2];
    float ls = 0.f, lq = 0.f;
    #pragma unroll
    for (int it = 0; it < 2; it++) {
        int i4 = tid + it * 256;
        float4 a = A4[base4 + i4], b = B4[base4 + i4];
        float4 xv = {a.x + b.x, a.y + b.y, a.z + b.z, a.w + b.w};
        xp[it] = xv;
        ls += xv.x + xv.y + xv.z + xv.w;
        lq += xv.x * xv.x + xv.y * xv.y + xv.z * xv.z + xv.w * xv.w;
    }
    #pragma unroll
    for (int off = 16; off; off >>= 1) {
        ls += __shfl_xor_sync(0xffffffffu, ls, off);
        lq += __shfl_xor_sync(0xffffffffu, lq, off);
    }
    if ((tid & 31) == 0) { red[tid >> 5] = ls; red[8 + (tid >> 5)] = lq; }
    __syncthreads();
    float S = 0.f, Qs = 0.f;
    #pragma unroll
    for (int w = 0; w < 8; w++) { S += red[w]; Qs += red[8 + w]; }
    float mean = S * (1.0f / DDIM);
    float var  = Qs * (1.0f / DDIM) - mean * mean;
    float inv  = rsqrtf(var + 1e-5f);
    const float4* G4 = (const float4*)g;
    const float4* Be4 = (const float4*)be;
    #pragma unroll
    for (int it = 0; it < 2; it++) {
        int i4 = tid + it * 256;
        float4 gg = G4[i4], bb = Be4[i4];
        float4 xv = xp[it];
        float4 v;
        v.x = (xv.x - mean) * inv * gg.x + bb.x;
        v.y = (xv.y - mean) * inv * gg.y + bb.y;
        v.z = (xv.z - mean) * inv * gg.z + bb.z;
        v.w = (xv.w - mean) * inv * gg.w + bb.w;
        ((float4*)out)[base4 + i4] = v;
    }
}

// ---------------- host orchestration -------------------------------------------
extern "C" void kernel_launch(void* const* d_in, const int* in_sizes, int n_in,
                              void* d_out, int out_size)
{
    const float* X     = (const float*)d_in[0];
    const float* Wq    = (const float*)d_in[1];
    const float* bq    = (const float*)d_in[2];
    const float* Wk    = (const float*)d_in[3];
    const float* bk    = (const float*)d_in[4];
    const float* Wv    = (const float*)d_in[5];
    const float* bv    = (const float*)d_in[6];
    const float* g1    = (const float*)d_in[7];
    const float* beta1 = (const float*)d_in[8];
    const float* W1    = (const float*)d_in[9];
    const float* b1    = (const float*)d_in[10];
    const float* W2    = (const float*)d_in[11];
    const float* b2    = (const float*)d_in[12];
    const float* g2    = (const float*)d_in[13];
    const float* beta2 = (const float*)d_in[14];
    float* out = (float*)d_out;

    __half *Ah, *Al, *Hh, *Hl, *Wf;
    float *Q, *K, *V, *X1;
    cudaGetSymbolAddress((void**)&Ah, g_Ah);
    cudaGetSymbolAddress((void**)&Al, g_Al);
    cudaGetSymbolAddress((void**)&Hh, g_Hh);
    cudaGetSymbolAddress((void**)&Hl, g_Hl);
    cudaGetSymbolAddress((void**)&Wf, g_Wf);
    cudaGetSymbolAddress((void**)&Q,  g_Q);
    cudaGetSymbolAddress((void**)&K,  g_K);
    cudaGetSymbolAddress((void**)&V,  g_V);
    cudaGetSymbolAddress((void**)&X1, g_X1);

    cudaFuncSetAttribute(gemm_fp16x2<0>, cudaFuncAttributeMaxDynamicSharedMemorySize, GEMM_SMEM);
    cudaFuncSetAttribute(gemm_fp16x2<1>, cudaFuncAttributeMaxDynamicSharedMemorySize, GEMM_SMEM);

    // launch 0: all splits/converts fused (X 2-way + 5 weights rounded)
    {
        int gx = (MROWS * DDIM / 4 + 255) / 256;
        dim3 gs(gx, 6);
        split_all_kernel<<<gs, 256>>>(X, Wq, Wk, Wv, W1, W2, Ah, Al, Wf);
    }

    dim3 gg(DDIM / BN, MROWS / BM);   // (16, 128) = 2048 CTAs
    // launches 1..3
    gemm_fp16x2<0><<<gg, 256, GEMM_SMEM>>>(Ah, Al, Wf + 0 * WSZ, bq, Q,  nullptr, nullptr);
    gemm_fp16x2<0><<<gg, 256, GEMM_SMEM>>>(Ah, Al, Wf + 1 * WSZ, bk, K,  nullptr, nullptr);
    gemm_fp16x2<0><<<gg, 256, GEMM_SMEM>>>(Ah, Al, Wf + 2 * WSZ, bv, V,  nullptr, nullptr);
    // launch 4
    attn_ln1_kernel<<<MROWS, 128>>>(Q, K, V, X, g1, beta1, X1, Ah, Al);
    // launch 5  <-- ncu -s 5 -c 1 captures THIS (FFN GEMM + GELU epilogue)
    gemm_fp16x2<1><<<gg, 256, GEMM_SMEM>>>(Ah, Al, Wf + 3 * WSZ, b1, nullptr, Hh, Hl);
    // launch 6
    gemm_fp16x2<0><<<gg, 256, GEMM_SMEM>>>(Hh, Hl, Wf + 4 * WSZ, b2, Q,  nullptr, nullptr);
    // launch 7
    add_ln_kernel<<<MROWS, 256>>>(X1, Q, g2, beta2, out);
}

// round 12
// speedup vs baseline: 4.8532x; 1.6861x over previous
#include <cuda_runtime.h>
#include <cuda_fp16.h>
#include <mma.h>
#include <cuda_pipeline.h>
#include <math.h>

using namespace nvcuda;

// Problem dims
#define MROWS 16384            // B*S
#define DDIM  2048             // D
#define MSZ   ((size_t)MROWS * DDIM)
#define WSZ   ((size_t)DDIM * DDIM)

// ---------------- device scratch (allocation-free rule) ------------------------
__device__ __half g_Ah[MSZ];               // activations fp16 (X, then X1)
__device__ __half g_Hh[MSZ];               // gelu output fp16
__device__ __half g_Wf[5 * WSZ];           // weights fp16 [K,N] row-major
__device__ float g_Q [MSZ];
__device__ float g_K [MSZ];
__device__ float g_V [MSZ];
__device__ float g_X1[MSZ];

// ---------------- fused convert: X + 5 weights to fp16 in ONE launch ------------
__global__ void __launch_bounds__(256)
split_all_kernel(const float* __restrict__ X,
                 const float* __restrict__ W0, const float* __restrict__ W1,
                 const float* __restrict__ W2, const float* __restrict__ W3,
                 const float* __restrict__ W4,
                 __half* __restrict__ Ah, __half* __restrict__ Wf)
{
    const int which = blockIdx.y;
    int i = blockIdx.x * 256 + threadIdx.x;
    const float* src;
    __half* oh;
    int n4;
    if (which == 0) {
        src = X; oh = Ah; n4 = (MROWS * DDIM) / 4;
    } else {
        const float* Ws[5] = {W0, W1, W2, W3, W4};
        src = Ws[which - 1];
        oh = Wf + (size_t)(which - 1) * WSZ;
        n4 = (DDIM * DDIM) / 4;
    }
    if (i >= n4) return;
    float4 v = ((const float4*)src)[i];
    __half2 h0 = {__float2half(v.x), __float2half(v.y)};
    __half2 h1 = {__float2half(v.z), __float2half(v.w)};
    ((__half2*)oh)[2 * i]     = h0;
    ((__half2*)oh)[2 * i + 1] = h1;
}

// ================= fp16 GEMM (HMMA): C = A x B, fp32 accum =====================
// CTA 128x128, BK=32, 3-stage cp.async, 8 warps of 64x32, 2 CTAs/SM.
constexpr int BM = 128, BN = 128, BK = 32;
constexpr int NSTG = 3;
constexpr int APAD = 8,  LDA = BK + APAD;     // 40
constexpr int BPAD = 8,  LDB = BN + BPAD;     // 136
constexpr int A_BYTES = BM * LDA * 2;         // 10240
constexpr int B_BYTES = BK * LDB * 2;         // 8704
constexpr int STG_BYTES = A_BYTES + B_BYTES;  // 18944
constexpr int GEMM_SMEM = NSTG * STG_BYTES;   // 56832  (x2 CTAs fits)

template<int EPI>
__global__ void __launch_bounds__(256, 2)
gemm_fp16(const __half* __restrict__ A,
          const __half* __restrict__ Bf,
          const float* __restrict__ bias,
          float* __restrict__ C,
          __half* __restrict__ Oh)
{
    constexpr int K = DDIM, N = DDIM;
    extern __shared__ char dsm[];

    const int tid  = threadIdx.x;
    const int warp = tid >> 5, lane = tid & 31;
    const int wr = warp >> 2;          // 0..1 -> 64-row slab
    const int wc = warp & 3;           // 0..3 -> 32-col slab
    const int m0 = blockIdx.y * BM, n0 = blockIdx.x * BN;

    wmma::fragment<wmma::accumulator, 16, 16, 16, float> acc[4][2];
    #pragma unroll
    for (int i = 0; i < 4; i++)
        #pragma unroll
        for (int j = 0; j < 2; j++) wmma::fill_fragment(acc[i][j], 0.0f);

    auto load_stage = [&](int s, int kk) {
        __half* sA = (__half*)(dsm + s * STG_BYTES);
        __half* sB = (__half*)(dsm + s * STG_BYTES + A_BYTES);
        #pragma unroll
        for (int r = 0; r < 2; r++) {              // A: 128x32 = 512 x 16B
            int idx = tid + r * 256;
            int row = idx >> 2, c8 = (idx & 3) * 8;
            __pipeline_memcpy_async(sA + row * LDA + c8,
                                    A + (size_t)(m0 + row) * K + kk + c8, 16);
        }
        #pragma unroll
        for (int r = 0; r < 2; r++) {              // B: 32x128 = 512 x 16B
            int idx = tid + r * 256;
            int row = idx >> 4, c8 = (idx & 15) * 8;
            __pipeline_memcpy_async(sB + row * LDB + c8,
                                    Bf + (size_t)(kk + row) * N + n0 + c8, 16);
        }
    };

    const int nIter = K / BK;   // 64
    load_stage(0, 0);             __pipeline_commit();
    load_stage(1, BK);            __pipeline_commit();

    for (int it = 0; it < nIter; ++it) {
        int cur = it % NSTG;
        __pipeline_wait_prior(1);          // stage `it` resident
        __syncthreads();                   // prev compute done before overwrite
        if (it + 2 < nIter) load_stage((it + 2) % NSTG, (it + 2) * BK);
        __pipeline_commit();

        const __half* sA = (const __half*)(dsm + cur * STG_BYTES);
        const __half* sB = (const __half*)(dsm + cur * STG_BYTES + A_BYTES);
        #pragma unroll
        for (int k2 = 0; k2 < BK; k2 += 16) {
            wmma::fragment<wmma::matrix_a, 16, 16, 16, __half, wmma::row_major> af[4];
            wmma::fragment<wmma::matrix_b, 16, 16, 16, __half, wmma::row_major> bf[2];
            #pragma unroll
            for (int i = 0; i < 4; i++)
                wmma::load_matrix_sync(af[i], sA + (wr * 64 + i * 16) * LDA + k2, LDA);
            #pragma unroll
            for (int j = 0; j < 2; j++)
                wmma::load_matrix_sync(bf[j], sB + k2 * LDB + wc * 32 + j * 16, LDB);
            #pragma unroll
            for (int i = 0; i < 4; i++)
                #pragma unroll
                for (int j = 0; j < 2; j++)
                    wmma::mma_sync(acc[i][j], af[i], bf[j], acc[i][j]);
        }
    }
    __syncthreads();

    // epilogue: per-warp smem staging, coalesced stores
    float* buf = (float*)dsm + warp * 272;
    #pragma unroll
    for (int i = 0; i < 4; i++) {
        #pragma unroll
        for (int j = 0; j < 2; j++) {
            wmma::store_matrix_sync(buf, acc[i][j], 16, wmma::mem_row_major);
            __syncwarp();
            const int gr = m0 + wr * 64 + i * 16;
            const int gc = n0 + wc * 32 + j * 16;
            const int r  = lane >> 1, ch = (lane & 1) * 8;
            #pragma unroll
            for (int e = 0; e < 8; e++) {
                int cc = ch + e;
                float v = buf[r * 16 + cc] + bias[gc + cc];
                size_t o = (size_t)(gr + r) * N + gc + cc;
                if (EPI == 0) {
                    C[o] = v;
                } else {
                    float gl = v * normcdff(v);            // exact GELU
                    Oh[o] = __float2half(gl);
                }
            }
            __syncwarp();
        }
    }
}

// ---------------- per-token head-attention + residual + LN1 (float4) -----------
__global__ void __launch_bounds__(128)
attn_ln1_kernel(const float* __restrict__ Q, const float* __restrict__ Kk,
                const float* __restrict__ V, const float* __restrict__ X,
                const float* __restrict__ g1, const float* __restrict__ be1,
                float* __restrict__ X1,
                __half* __restrict__ Oh)
{
    __shared__ float sq[16 * 129], sk[16 * 129], sv[16 * 129];
    __shared__ float satt[16][16];
    __shared__ float red[8];
    const int t = blockIdx.x, tid = threadIdx.x;
    const size_t base4 = (size_t)t * (DDIM / 4);

    const float4* Q4 = (const float4*)Q;
    const float4* K4 = (const float4*)Kk;
    const float4* V4 = (const float4*)V;
    const float4* X4 = (const float4*)X;

    #pragma unroll
    for (int it = 0; it < 4; it++) {
        int i4 = tid + it * 128;
        int e = i4 * 4, h = e >> 7, d = e & 127, o = h * 129 + d;
        float4 q = Q4[base4 + i4], k = K4[base4 + i4], v = V4[base4 + i4];
        sq[o] = q.x; sq[o+1] = q.y; sq[o+2] = q.z; sq[o+3] = q.w;
        sk[o] = k.x; sk[o+1] = k.y; sk[o+2] = k.z; sk[o+3] = k.w;
        sv[o] = v.x; sv[o+1] = v.y; sv[o+2] = v.z; sv[o+3] = v.w;
    }
    __syncthreads();

    #pragma unroll
    for (int p = tid; p < 256; p += 128) {
        int h = p >> 4, tt = p & 15;
        const float* qp = sq + h * 129;
        const float* kp = sk + tt * 129;
        float s = 0.f;
        #pragma unroll
        for (int d = 0; d < 128; d++) s += qp[d] * kp[d];
        satt[h][tt] = s * 0.08838834764831845f;     // 1/sqrt(128)
    }
    __syncthreads();

    if (tid < 16) {
        float mx = -1e30f;
        #pragma unroll
        for (int j = 0; j < 16; j++) mx = fmaxf(mx, satt[tid][j]);
        float sum = 0.f;
        #pragma unroll
        for (int j = 0; j < 16; j++) { float e = expf(satt[tid][j] - mx); satt[tid][j] = e; sum += e; }
        float inv = 1.f / sum;
        #pragma unroll
        for (int j = 0; j < 16; j++) satt[tid][j] *= inv;
    }
    __syncthreads();

    float4 xp[4];
    float ls = 0.f, lq = 0.f;
    #pragma unroll
    for (int it = 0; it < 4; it++) {
        int i4 = tid + it * 128;
        int e = i4 * 4, h = e >> 7, d = e & 127;
        float4 xv = X4[base4 + i4];
        float y0 = 0.f, y1 = 0.f, y2 = 0.f, y3 = 0.f;
        #pragma unroll
        for (int tt = 0; tt < 16; tt++) {
            float p = satt[h][tt];
            const float* vp = sv + tt * 129 + d;
            y0 += p * vp[0]; y1 += p * vp[1]; y2 += p * vp[2]; y3 += p * vp[3];
        }
        xv.x += y0; xv.y += y1; xv.z += y2; xv.w += y3;
        xp[it] = xv;
        ls += xv.x + xv.y + xv.z + xv.w;
        lq += xv.x * xv.x + xv.y * xv.y + xv.z * xv.z + xv.w * xv.w;
    }
    #pragma unroll
    for (int off = 16; off; off >>= 1) {
        ls += __shfl_xor_sync(0xffffffffu, ls, off);
        lq += __shfl_xor_sync(0xffffffffu, lq, off);
    }
    if ((tid & 31) == 0) { red[tid >> 5] = ls; red[4 + (tid >> 5)] = lq; }
    __syncthreads();
    float S  = red[0] + red[1] + red[2] + red[3];
    float Qs = red[4] + red[5] + red[6] + red[7];
    float mean = S * (1.0f / DDIM);
    float var  = Qs * (1.0f / DDIM) - mean * mean;
    float inv  = rsqrtf(var + 1e-5f);

    const float4* G4 = (const float4*)g1;
    const float4* Be4 = (const float4*)be1;
    #pragma unroll
    for (int it = 0; it < 4; it++) {
        int i4 = tid + it * 128;
        float4 g = G4[i4], be = Be4[i4];
        float4 xv = xp[it];
        float4 v;
        v.x = (xv.x - mean) * inv * g.x + be.x;
        v.y = (xv.y - mean) * inv * g.y + be.y;
        v.z = (xv.z - mean) * inv * g.z + be.z;
        v.w = (xv.w - mean) * inv * g.w + be.w;
        ((float4*)X1)[base4 + i4] = v;
        __half2 h0 = {__float2half(v.x), __float2half(v.y)};
        __half2 h1 = {__float2half(v.z), __float2half(v.w)};
        size_t ob = (base4 + i4) * 2;
        ((__half2*)Oh)[ob]     = h0;
        ((__half2*)Oh)[ob + 1] = h1;
    }
}

// ---------------- out = LN(A + B) * g + beta (float4) --------------------------
__global__ void __launch_bounds__(256)
add_ln_kernel(const float* __restrict__ A, const float* __restrict__ Bv,
              const float* __restrict__ g, const float* __restrict__ be,
              float* __restrict__ out)
{
    __shared__ float red[16];
    const int t = blockIdx.x, tid = threadIdx.x;
    const size_t base4 = (size_t)t * (DDIM / 4);
    const float4* A4 = (const float4*)A;
    const float4* B4 = (const float4*)Bv;
    float4 xp[2];
    float ls = 0.f, lq = 0.f;
    #pragma unroll
    for (int it = 0; it < 2; it++) {
        int i4 = tid + it * 256;
        float4 a = A4[base4 + i4], b = B4[base4 + i4];
        float4 xv = {a.x + b.x, a.y + b.y, a.z + b.z, a.w + b.w};
        xp[it] = xv;
        ls += xv.x + xv.y + xv.z + xv.w;
        lq += xv.x * xv.x + xv.y * xv.y + xv.z * xv.z + xv.w * xv.w;
    }
    #pragma unroll
    for (int off = 16; off; off >>= 1) {
        ls += __shfl_xor_sync(0xffffffffu, ls, off);
        lq += __shfl_xor_sync(0xffffffffu, lq, off);
    }
    if ((tid & 31) == 0) { red[tid >> 5] = ls; red[8 + (tid >> 5)] = lq; }
    __syncthreads();
    float S = 0.f, Qs = 0.f;
    #pragma unroll
    for (int w = 0; w < 8; w++) { S += red[w]; Qs += red[8 + w]; }
    float mean = S * (1.0f / DDIM);
    float var  = Qs * (1.0f / DDIM) - mean * mean;
    float inv  = rsqrtf(var + 1e-5f);
    const float4* G4 = (const float4*)g;
    const float4* Be4 = (const float4*)be;
    #pragma unroll
    for (int it = 0; it < 2; it++) {
        int i4 = tid + it * 256;
        float4 gg = G4[i4], bb = Be4[i4];
        float4 xv = xp[it];
        float4 v;
        v.x = (xv.x - mean) * inv * gg.x + bb.x;
        v.y = (xv.y - mean) * inv * gg.y + bb.y;
        v.z = (xv.z - mean) * inv * gg.z + bb.z;
        v.w = (xv.w - mean) * inv * gg.w + bb.w;
        ((float4*)out)[base4 + i4] = v;
    }
}

// ---------------- host orchestration -------------------------------------------
extern "C" void kernel_launch(void* const* d_in, const int* in_sizes, int n_in,
                              void* d_out, int out_size)
{
    const float* X     = (const float*)d_in[0];
    const float* Wq    = (const float*)d_in[1];
    const float* bq    = (const float*)d_in[2];
    const float* Wk    = (const float*)d_in[3];
    const float* bk    = (const float*)d_in[4];
    const float* Wv    = (const float*)d_in[5];
    const float* bv    = (const float*)d_in[6];
    const float* g1    = (const float*)d_in[7];
    const float* beta1 = (const float*)d_in[8];
    const float* W1    = (const float*)d_in[9];
    const float* b1    = (const float*)d_in[10];
    const float* W2    = (const float*)d_in[11];
    const float* b2    = (const float*)d_in[12];
    const float* g2    = (const float*)d_in[13];
    const float* beta2 = (const float*)d_in[14];
    float* out = (float*)d_out;

    __half *Ah, *Hh, *Wf;
    float *Q, *K, *V, *X1;
    cudaGetSymbolAddress((void**)&Ah, g_Ah);
    cudaGetSymbolAddress((void**)&Hh, g_Hh);
    cudaGetSymbolAddress((void**)&Wf, g_Wf);
    cudaGetSymbolAddress((void**)&Q,  g_Q);
    cudaGetSymbolAddress((void**)&K,  g_K);
    cudaGetSymbolAddress((void**)&V,  g_V);
    cudaGetSymbolAddress((void**)&X1, g_X1);

    cudaFuncSetAttribute(gemm_fp16<0>, cudaFuncAttributeMaxDynamicSharedMemorySize, GEMM_SMEM);
    cudaFuncSetAttribute(gemm_fp16<1>, cudaFuncAttributeMaxDynamicSharedMemorySize, GEMM_SMEM);

    // launch 0: all converts fused (X + 5 weights)
    {
        int gx = (MROWS * DDIM / 4 + 255) / 256;
        dim3 gs(gx, 6);
        split_all_kernel<<<gs, 256>>>(X, Wq, Wk, Wv, W1, W2, Ah, Wf);
    }

    dim3 gg(DDIM / BN, MROWS / BM);   // (16, 128) = 2048 CTAs
    // launches 1..3
    gemm_fp16<0><<<gg, 256, GEMM_SMEM>>>(Ah, Wf + 0 * WSZ, bq, Q,  nullptr);
    gemm_fp16<0><<<gg, 256, GEMM_SMEM>>>(Ah, Wf + 1 * WSZ, bk, K,  nullptr);
    gemm_fp16<0><<<gg, 256, GEMM_SMEM>>>(Ah, Wf + 2 * WSZ, bv, V,  nullptr);
    // launch 4
    attn_ln1_kernel<<<MROWS, 128>>>(Q, K, V, X, g1, beta1, X1, Ah);
    // launch 5  <-- ncu -s 5 -c 1 captures THIS (FFN GEMM + GELU epilogue)
    gemm_fp16<1><<<gg, 256, GEMM_SMEM>>>(Ah, Wf + 3 * WSZ, b1, nullptr, Hh);
    // launch 6
    gemm_fp16<0><<<gg, 256, GEMM_SMEM>>>(Hh, Wf + 4 * WSZ, b2, Q,  nullptr);
    // launch 7
    add_ln_kernel<<<MROWS, 256>>>(X1, Q, g2, beta2, out);
}

// round 13
// speedup vs baseline: 4.8755x; 1.0046x over previous
#include <cuda_runtime.h>
#include <cuda_fp16.h>
#include <mma.h>
#include <cuda_pipeline.h>
#include <math.h>

using namespace nvcuda;

// Problem dims
#define MROWS 16384            // B*S
#define DDIM  2048             // D
#define MSZ   ((size_t)MROWS * DDIM)
#define WSZ   ((size_t)DDIM * DDIM)

// ---------------- device scratch (allocation-free rule) ------------------------
__device__ __half g_Ah[MSZ];               // activations fp16 (X, then X1)
__device__ __half g_Hh[MSZ];               // gelu output fp16
__device__ __half g_Wf[5 * WSZ];           // weights fp16 [K,N] row-major
__device__ __half g_Qh[MSZ];               // Q fp16; later reused as y2
__device__ __half g_Kh[MSZ];
__device__ __half g_Vh[MSZ];
__device__ float g_X1[MSZ];

// ---------------- fused convert: X + 5 weights to fp16 in ONE launch ------------
__global__ void __launch_bounds__(256)
split_all_kernel(const float* __restrict__ X,
                 const float* __restrict__ W0, const float* __restrict__ W1,
                 const float* __restrict__ W2, const float* __restrict__ W3,
                 const float* __restrict__ W4,
                 __half* __restrict__ Ah, __half* __restrict__ Wf)
{
    const int which = blockIdx.y;
    int i = blockIdx.x * 256 + threadIdx.x;
    const float* src;
    __half* oh;
    int n4;
    if (which == 0) {
        src = X; oh = Ah; n4 = (MROWS * DDIM) / 4;
    } else {
        const float* Ws[5] = {W0, W1, W2, W3, W4};
        src = Ws[which - 1];
        oh = Wf + (size_t)(which - 1) * WSZ;
        n4 = (DDIM * DDIM) / 4;
    }
    if (i >= n4) return;
    float4 v = ((const float4*)src)[i];
    __half2 h0 = {__float2half(v.x), __float2half(v.y)};
    __half2 h1 = {__float2half(v.z), __float2half(v.w)};
    ((__half2*)oh)[2 * i]     = h0;
    ((__half2*)oh)[2 * i + 1] = h1;
}

// ================= fp16 GEMM (HMMA): O = A x B (+bias [+gelu]), fp16 out =======
// CTA 128x128, BK=64, 3-stage cp.async, 8 warps of 64x32, 2 CTAs/SM.
constexpr int BM = 128, BN = 128, BK = 64;
constexpr int NSTG = 3;
constexpr int APAD = 8,  LDA = BK + APAD;     // 72
constexpr int BPAD = 8,  LDB = BN + BPAD;     // 136
constexpr int A_BYTES = BM * LDA * 2;         // 18432
constexpr int B_BYTES = BK * LDB * 2;         // 17408
constexpr int STG_BYTES = A_BYTES + B_BYTES;  // 35840
constexpr int GEMM_SMEM = NSTG * STG_BYTES;   // 107520 (x2 CTAs = 215040 < 228K)

template<int EPI>   // 0: bias; 1: bias + exact GELU
__global__ void __launch_bounds__(256, 2)
gemm_fp16(const __half* __restrict__ A,
          const __half* __restrict__ Bf,
          const float* __restrict__ bias,
          __half* __restrict__ Oh)
{
    constexpr int K = DDIM, N = DDIM;
    extern __shared__ char dsm[];

    const int tid  = threadIdx.x;
    const int warp = tid >> 5, lane = tid & 31;
    const int wr = warp >> 2;          // 0..1 -> 64-row slab
    const int wc = warp & 3;           // 0..3 -> 32-col slab
    const int m0 = blockIdx.y * BM, n0 = blockIdx.x * BN;

    wmma::fragment<wmma::accumulator, 16, 16, 16, float> acc[4][2];
    #pragma unroll
    for (int i = 0; i < 4; i++)
        #pragma unroll
        for (int j = 0; j < 2; j++) wmma::fill_fragment(acc[i][j], 0.0f);

    auto load_stage = [&](int s, int kk) {
        __half* sA = (__half*)(dsm + s * STG_BYTES);
        __half* sB = (__half*)(dsm + s * STG_BYTES + A_BYTES);
        #pragma unroll
        for (int r = 0; r < 4; r++) {              // A: 128x64 = 1024 x 16B
            int idx = tid + r * 256;
            int row = idx >> 3, c8 = (idx & 7) * 8;
            __pipeline_memcpy_async(sA + row * LDA + c8,
                                    A + (size_t)(m0 + row) * K + kk + c8, 16);
        }
        #pragma unroll
        for (int r = 0; r < 4; r++) {              // B: 64x128 = 1024 x 16B
            int idx = tid + r * 256;
            int row = idx >> 4, c8 = (idx & 15) * 8;
            __pipeline_memcpy_async(sB + row * LDB + c8,
                                    Bf + (size_t)(kk + row) * N + n0 + c8, 16);
        }
    };

    const int nIter = K / BK;   // 32
    load_stage(0, 0);             __pipeline_commit();
    load_stage(1, BK);            __pipeline_commit();

    for (int it = 0; it < nIter; ++it) {
        int cur = it % NSTG;
        __pipeline_wait_prior(1);          // stage `it` resident
        __syncthreads();                   // prev compute done before overwrite
        if (it + 2 < nIter) load_stage((it + 2) % NSTG, (it + 2) * BK);
        __pipeline_commit();

        const __half* sA = (const __half*)(dsm + cur * STG_BYTES);
        const __half* sB = (const __half*)(dsm + cur * STG_BYTES + A_BYTES);
        #pragma unroll
        for (int k2 = 0; k2 < BK; k2 += 16) {
            wmma::fragment<wmma::matrix_a, 16, 16, 16, __half, wmma::row_major> af[4];
            wmma::fragment<wmma::matrix_b, 16, 16, 16, __half, wmma::row_major> bf[2];
            #pragma unroll
            for (int i = 0; i < 4; i++)
                wmma::load_matrix_sync(af[i], sA + (wr * 64 + i * 16) * LDA + k2, LDA);
            #pragma unroll
            for (int j = 0; j < 2; j++)
                wmma::load_matrix_sync(bf[j], sB + k2 * LDB + wc * 32 + j * 16, LDB);
            #pragma unroll
            for (int i = 0; i < 4; i++)
                #pragma unroll
                for (int j = 0; j < 2; j++)
                    wmma::mma_sync(acc[i][j], af[i], bf[j], acc[i][j]);
        }
    }
    __syncthreads();

    // epilogue: per-warp smem staging, coalesced fp16 stores
    float* buf = (float*)dsm + warp * 272;
    #pragma unroll
    for (int i = 0; i < 4; i++) {
        #pragma unroll
        for (int j = 0; j < 2; j++) {
            wmma::store_matrix_sync(buf, acc[i][j], 16, wmma::mem_row_major);
            __syncwarp();
            const int gr = m0 + wr * 64 + i * 16;
            const int gc = n0 + wc * 32 + j * 16;
            const int r  = lane >> 1, ch = (lane & 1) * 8;
            #pragma unroll
            for (int e = 0; e < 8; e++) {
                int cc = ch + e;
                float v = buf[r * 16 + cc] + bias[gc + cc];
                if (EPI == 1) v = v * normcdff(v);     // exact GELU
                Oh[(size_t)(gr + r) * N + gc + cc] = __float2half(v);
            }
            __syncwarp();
        }
    }
}

// ---------------- per-token head-attention + residual + LN1 --------------------
// Q/K/V in fp16, X fp32; outputs X1 fp32 + Ah fp16.
__global__ void __launch_bounds__(128)
attn_ln1_kernel(const __half* __restrict__ Q, const __half* __restrict__ Kk,
                const __half* __restrict__ V, const float* __restrict__ X,
                const float* __restrict__ g1, const float* __restrict__ be1,
                float* __restrict__ X1,
                __half* __restrict__ Oh)
{
    __shared__ float sq[16 * 129], sk[16 * 129], sv[16 * 129];
    __shared__ float satt[16][16];
    __shared__ float red[8];
    const int t = blockIdx.x, tid = threadIdx.x;
    const size_t base4 = (size_t)t * (DDIM / 4);
    const size_t base8 = (size_t)t * (DDIM / 8);

    const int4* Q8 = (const int4*)Q;       // 8 halves per int4
    const int4* K8 = (const int4*)Kk;
    const int4* V8 = (const int4*)V;
    const float4* X4 = (const float4*)X;

    #pragma unroll
    for (int it = 0; it < 2; it++) {
        int i8 = tid + it * 128;           // 0..255
        int e = i8 * 8, h = e >> 7, d = e & 127, o = h * 129 + d;
        int4 qa = Q8[base8 + i8], ka = K8[base8 + i8], va = V8[base8 + i8];
        const __half2* qh = (const __half2*)&qa;
        const __half2* kh = (const __half2*)&ka;
        const __half2* vh = (const __half2*)&va;
        #pragma unroll
        for (int p = 0; p < 4; p++) {
            float2 qf = __half22float2(qh[p]);
            float2 kf = __half22float2(kh[p]);
            float2 vf = __half22float2(vh[p]);
            sq[o + 2*p] = qf.x; sq[o + 2*p + 1] = qf.y;
            sk[o + 2*p] = kf.x; sk[o + 2*p + 1] = kf.y;
            sv[o + 2*p] = vf.x; sv[o + 2*p + 1] = vf.y;
        }
    }
    __syncthreads();

    #pragma unroll
    for (int p = tid; p < 256; p += 128) {
        int h = p >> 4, tt = p & 15;
        const float* qp = sq + h * 129;
        const float* kp = sk + tt * 129;
        float s = 0.f;
        #pragma unroll
        for (int d = 0; d < 128; d++) s += qp[d] * kp[d];
        satt[h][tt] = s * 0.08838834764831845f;     // 1/sqrt(128)
    }
    __syncthreads();

    if (tid < 16) {
        float mx = -1e30f;
        #pragma unroll
        for (int j = 0; j < 16; j++) mx = fmaxf(mx, satt[tid][j]);
        float sum = 0.f;
        #pragma unroll
        for (int j = 0; j < 16; j++) { float e = expf(satt[tid][j] - mx); satt[tid][j] = e; sum += e; }
        float inv = 1.f / sum;
        #pragma unroll
        for (int j = 0; j < 16; j++) satt[tid][j] *= inv;
    }
    __syncthreads();

    float4 xp[4];
    float ls = 0.f, lq = 0.f;
    #pragma unroll
    for (int it = 0; it < 4; it++) {
        int i4 = tid + it * 128;
        int e = i4 * 4, h = e >> 7, d = e & 127;
        float4 xv = X4[base4 + i4];
        float y0 = 0.f, y1 = 0.f, y2 = 0.f, y3 = 0.f;
        #pragma unroll
        for (int tt = 0; tt < 16; tt++) {
            float p = satt[h][tt];
            const float* vp = sv + tt * 129 + d;
            y0 += p * vp[0]; y1 += p * vp[1]; y2 += p * vp[2]; y3 += p * vp[3];
        }
        xv.x += y0; xv.y += y1; xv.z += y2; xv.w += y3;
        xp[it] = xv;
        ls += xv.x + xv.y + xv.z + xv.w;
        lq += xv.x * xv.x + xv.y * xv.y + xv.z * xv.z + xv.w * xv.w;
    }
    #pragma unroll
    for (int off = 16; off; off >>= 1) {
        ls += __shfl_xor_sync(0xffffffffu, ls, off);
        lq += __shfl_xor_sync(0xffffffffu, lq, off);
    }
    if ((tid & 31) == 0) { red[tid >> 5] = ls; red[4 + (tid >> 5)] = lq; }
    __syncthreads();
    float S  = red[0] + red[1] + red[2] + red[3];
    float Qs = red[4] + red[5] + red[6] + red[7];
    float mean = S * (1.0f / DDIM);
    float var  = Qs * (1.0f / DDIM) - mean * mean;
    float inv  = rsqrtf(var + 1e-5f);

    const float4* G4 = (const float4*)g1;
    const float4* Be4 = (const float4*)be1;
    #pragma unroll
    for (int it = 0; it < 4; it++) {
        int i4 = tid + it * 128;
        float4 g = G4[i4], be = Be4[i4];
        float4 xv = xp[it];
        float4 v;
        v.x = (xv.x - mean) * inv * g.x + be.x;
        v.y = (xv.y - mean) * inv * g.y + be.y;
        v.z = (xv.z - mean) * inv * g.z + be.z;
        v.w = (xv.w - mean) * inv * g.w + be.w;
        ((float4*)X1)[base4 + i4] = v;
        __half2 h0 = {__float2half(v.x), __float2half(v.y)};
        __half2 h1 = {__float2half(v.z), __float2half(v.w)};
        size_t ob = (base4 + i4) * 2;
        ((__half2*)Oh)[ob]     = h0;
        ((__half2*)Oh)[ob + 1] = h1;
    }
}

// ---------------- out = LN(A + Bhalf) * g + beta -------------------------------
__global__ void __launch_bounds__(256)
add_ln_kernel(const float* __restrict__ A, const __half* __restrict__ Bv,
              const float* __restrict__ g, const float* __restrict__ be,
              float* __restrict__ out)
{
    __shared__ float red[16];
    const int t = blockIdx.x, tid = threadIdx.x;
    const size_t base4 = (size_t)t * (DDIM / 4);
    const size_t base8 = (size_t)t * (DDIM / 8);
    const float4* A4 = (const float4*)A;
    const int4* B8 = (const int4*)Bv;

    // 8 elems per thread: one int4 (8 halves) + two float4
    int4 ba = B8[base8 + tid];
    const __half2* bh = (const __half2*)&ba;
    float bb[8];
    #pragma unroll
    for (int p = 0; p < 4; p++) {
        float2 f = __half22float2(bh[p]);
        bb[2*p] = f.x; bb[2*p+1] = f.y;
    }
    float xp[8];
    float ls = 0.f, lq = 0.f;
    #pragma unroll
    for (int it = 0; it < 2; it++) {
        int i4 = tid * 2 + it;
        float4 a = A4[base4 + i4];
        float v0 = a.x + bb[it*4+0], v1 = a.y + bb[it*4+1];
        float v2 = a.z + bb[it*4+2], v3 = a.w + bb[it*4+3];
        xp[it*4+0] = v0; xp[it*4+1] = v1; xp[it*4+2] = v2; xp[it*4+3] = v3;
        ls += v0 + v1 + v2 + v3;
        lq += v0*v0 + v1*v1 + v2*v2 + v3*v3;
    }
    #pragma unroll
    for (int off = 16; off; off >>= 1) {
        ls += __shfl_xor_sync(0xffffffffu, ls, off);
        lq += __shfl_xor_sync(0xffffffffu, lq, off);
    }
    if ((tid & 31) == 0) { red[tid >> 5] = ls; red[8 + (tid >> 5)] = lq; }
    __syncthreads();
    float S = 0.f, Qs = 0.f;
    #pragma unroll
    for (int w = 0; w < 8; w++) { S += red[w]; Qs += red[8 + w]; }
    float mean = S * (1.0f / DDIM);
    float var  = Qs * (1.0f / DDIM) - mean * mean;
    float inv  = rsqrtf(var + 1e-5f);
    #pragma unroll
    for (int it = 0; it < 2; it++) {
        int i4 = tid * 2 + it;
        int eb = i4 * 4;
        float4 gg = ((const float4*)g)[i4];
        float4 be4 = ((const float4*)be)[i4];
        float4 v;
        v.x = (xp[it*4+0] - mean) * inv * gg.x + be4.x;
        v.y = (xp[it*4+1] - mean) * inv * gg.y + be4.y;
        v.z = (xp[it*4+2] - mean) * inv * gg.z + be4.z;
        v.w = (xp[it*4+3] - mean) * inv * gg.w + be4.w;
        ((float4*)out)[base4 + i4] = v;
        (void)eb;
    }
}

// ---------------- host orchestration -------------------------------------------
extern "C" void kernel_launch(void* const* d_in, const int* in_sizes, int n_in,
                              void* d_out, int out_size)
{
    const float* X     = (const float*)d_in[0];
    const float* Wq    = (const float*)d_in[1];
    const float* bq    = (const float*)d_in[2];
    const float* Wk    = (const float*)d_in[3];
    const float* bk    = (const float*)d_in[4];
    const float* Wv    = (const float*)d_in[5];
    const float* bv    = (const float*)d_in[6];
    const float* g1    = (const float*)d_in[7];
    const float* beta1 = (const float*)d_in[8];
    const float* W1    = (const float*)d_in[9];
    const float* b1    = (const float*)d_in[10];
    const float* W2    = (const float*)d_in[11];
    const float* b2    = (const float*)d_in[12];
    const float* g2    = (const float*)d_in[13];
    const float* beta2 = (const float*)d_in[14];
    float* out = (float*)d_out;

    __half *Ah, *Hh, *Wf, *Qh, *Kh, *Vh;
    float *X1;
    cudaGetSymbolAddress((void**)&Ah, g_Ah);
    cudaGetSymbolAddress((void**)&Hh, g_Hh);
    cudaGetSymbolAddress((void**)&Wf, g_Wf);
    cudaGetSymbolAddress((void**)&Qh, g_Qh);
    cudaGetSymbolAddress((void**)&Kh, g_Kh);
    cudaGetSymbolAddress((void**)&Vh, g_Vh);
    cudaGetSymbolAddress((void**)&X1, g_X1);

    cudaFuncSetAttribute(gemm_fp16<0>, cudaFuncAttributeMaxDynamicSharedMemorySize, GEMM_SMEM);
    cudaFuncSetAttribute(gemm_fp16<1>, cudaFuncAttributeMaxDynamicSharedMemorySize, GEMM_SMEM);

    // launch 0: all converts fused (X + 5 weights)
    {
        int gx = (MROWS * DDIM / 4 + 255) / 256;
        dim3 gs(gx, 6);
        split_all_kernel<<<gs, 256>>>(X, Wq, Wk, Wv, W1, W2, Ah, Wf);
    }

    dim3 gg(DDIM / BN, MROWS / BM);   // (16, 128) = 2048 CTAs
    // launches 1..3
    gemm_fp16<0><<<gg, 256, GEMM_SMEM>>>(Ah, Wf + 0 * WSZ, bq, Qh);
    gemm_fp16<0><<<gg, 256, GEMM_SMEM>>>(Ah, Wf + 1 * WSZ, bk, Kh);
    gemm_fp16<0><<<gg, 256, GEMM_SMEM>>>(Ah, Wf + 2 * WSZ, bv, Vh);
    // launch 4
    attn_ln1_kernel<<<MROWS, 128>>>(Qh, Kh, Vh, X, g1, beta1, X1, Ah);
    // launch 5  <-- ncu -s 5 -c 1 captures THIS (FFN GEMM + GELU epilogue)
    gemm_fp16<1><<<gg, 256, GEMM_SMEM>>>(Ah, Wf + 3 * WSZ, b1, Hh);
    // launch 6  (y2 reuses Qh)
    gemm_fp16<0><<<gg, 256, GEMM_SMEM>>>(Hh, Wf + 4 * WSZ, b2, Qh);
    // launch 7
    add_ln_kernel<<<MROWS, 256>>>(X1, Qh, g2, beta2, out);
}

// round 15
// speedup vs baseline: 5.5787x; 1.1443x over previous
#include <cuda_runtime.h>
#include <cuda_fp16.h>
#include <mma.h>
#include <cuda_pipeline.h>
#include <math.h>

using namespace nvcuda;

// Problem dims
#define MROWS 16384            // B*S
#define DDIM  2048             // D
#define MSZ   ((size_t)MROWS * DDIM)
#define WSZ   ((size_t)DDIM * DDIM)

// ---------------- device scratch (allocation-free rule) ------------------------
__device__ __half g_Ah[MSZ];               // activations fp16 (X, then X1)
__device__ __half g_Hh[MSZ];               // gelu output fp16
__device__ __half g_Wf[5 * WSZ];           // weights fp16 [K,N] row-major
__device__ __half g_Qh[MSZ];               // Q fp16; later reused as y2
__device__ __half g_Kh[MSZ];
__device__ __half g_Vh[MSZ];

// ---------------- fused convert: X + 5 weights to fp16 in ONE launch ------------
__global__ void __launch_bounds__(256)
split_all_kernel(const float* __restrict__ X,
                 const float* __restrict__ W0, const float* __restrict__ W1,
                 const float* __restrict__ W2, const float* __restrict__ W3,
                 const float* __restrict__ W4,
                 __half* __restrict__ Ah, __half* __restrict__ Wf)
{
    const int which = blockIdx.y;
    int i = blockIdx.x * 256 + threadIdx.x;
    const float* src;
    __half* oh;
    int n4;
    if (which == 0) {
        src = X; oh = Ah; n4 = (MROWS * DDIM) / 4;
    } else {
        const float* Ws[5] = {W0, W1, W2, W3, W4};
        src = Ws[which - 1];
        oh = Wf + (size_t)(which - 1) * WSZ;
        n4 = (DDIM * DDIM) / 4;
    }
    if (i >= n4) return;
    float4 v = ((const float4*)src)[i];
    __half2 h0 = {__float2half(v.x), __float2half(v.y)};
    __half2 h1 = {__float2half(v.z), __float2half(v.w)};
    ((__half2*)oh)[2 * i]     = h0;
    ((__half2*)oh)[2 * i + 1] = h1;
}

// ================= fp16 GEMM (HMMA): O = A x B (+bias [+gelu]), fp16 out =======
// CTA 128x128, BK=64, 3-stage cp.async, 8 warps of 64x32, 2 CTAs/SM.
constexpr int BM = 128, BN = 128, BK = 64;
constexpr int NSTG = 3;
constexpr int APAD = 8,  LDA = BK + APAD;     // 72
constexpr int BPAD = 8,  LDB = BN + BPAD;     // 136
constexpr int A_BYTES = BM * LDA * 2;         // 18432
constexpr int B_BYTES = BK * LDB * 2;         // 17408
constexpr int STG_BYTES = A_BYTES + B_BYTES;  // 35840
constexpr int GEMM_SMEM = NSTG * STG_BYTES;   // 107520 (x2 CTAs = 215040 < 228K)

template<int EPI>   // 0: bias; 1: bias + exact GELU
__global__ void __launch_bounds__(256, 2)
gemm_fp16(const __half* __restrict__ A,
          const __half* __restrict__ Bf,
          const float* __restrict__ bias,
          __half* __restrict__ Oh)
{
    constexpr int K = DDIM, N = DDIM;
    extern __shared__ char dsm[];

    const int tid  = threadIdx.x;
    const int warp = tid >> 5, lane = tid & 31;
    const int wr = warp >> 2;          // 0..1 -> 64-row slab
    const int wc = warp & 3;           // 0..3 -> 32-col slab
    const int m0 = blockIdx.y * BM, n0 = blockIdx.x * BN;

    wmma::fragment<wmma::accumulator, 16, 16, 16, float> acc[4][2];
    #pragma unroll
    for (int i = 0; i < 4; i++)
        #pragma unroll
        for (int j = 0; j < 2; j++) wmma::fill_fragment(acc[i][j], 0.0f);

    auto load_stage = [&](int s, int kk) {
        __half* sA = (__half*)(dsm + s * STG_BYTES);
        __half* sB = (__half*)(dsm + s * STG_BYTES + A_BYTES);
        #pragma unroll
        for (int r = 0; r < 4; r++) {              // A: 128x64 = 1024 x 16B
            int idx = tid + r * 256;
            int row = idx >> 3, c8 = (idx & 7) * 8;
            __pipeline_memcpy_async(sA + row * LDA + c8,
                                    A + (size_t)(m0 + row) * K + kk + c8, 16);
        }
        #pragma unroll
        for (int r = 0; r < 4; r++) {              // B: 64x128 = 1024 x 16B
            int idx = tid + r * 256;
            int row = idx >> 4, c8 = (idx & 15) * 8;
            __pipeline_memcpy_async(sB + row * LDB + c8,
                                    Bf + (size_t)(kk + row) * N + n0 + c8, 16);
        }
    };

    const int nIter = K / BK;   // 32
    load_stage(0, 0);             __pipeline_commit();
    load_stage(1, BK);            __pipeline_commit();

    for (int it = 0; it < nIter; ++it) {
        int cur = it % NSTG;
        __pipeline_wait_prior(1);          // stage `it` resident
        __syncthreads();                   // prev compute done before overwrite
        if (it + 2 < nIter) load_stage((it + 2) % NSTG, (it + 2) * BK);
        __pipeline_commit();

        const __half* sA = (const __half*)(dsm + cur * STG_BYTES);
        const __half* sB = (const __half*)(dsm + cur * STG_BYTES + A_BYTES);
        #pragma unroll
        for (int k2 = 0; k2 < BK; k2 += 16) {
            wmma::fragment<wmma::matrix_a, 16, 16, 16, __half, wmma::row_major> af[4];
            wmma::fragment<wmma::matrix_b, 16, 16, 16, __half, wmma::row_major> bf[2];
            #pragma unroll
            for (int i = 0; i < 4; i++)
                wmma::load_matrix_sync(af[i], sA + (wr * 64 + i * 16) * LDA + k2, LDA);
            #pragma unroll
            for (int j = 0; j < 2; j++)
                wmma::load_matrix_sync(bf[j], sB + k2 * LDB + wc * 32 + j * 16, LDB);
            #pragma unroll
            for (int i = 0; i < 4; i++)
                #pragma unroll
                for (int j = 0; j < 2; j++)
                    wmma::mma_sync(acc[i][j], af[i], bf[j], acc[i][j]);
        }
    }
    __syncthreads();

    // epilogue: per-warp smem staging, ONE 16B store (8 halves) per thread/frag
    float* buf = (float*)dsm + warp * 272;
    #pragma unroll
    for (int i = 0; i < 4; i++) {
        #pragma unroll
        for (int j = 0; j < 2; j++) {
            wmma::store_matrix_sync(buf, acc[i][j], 16, wmma::mem_row_major);
            __syncwarp();
            const int gr = m0 + wr * 64 + i * 16;
            const int gc = n0 + wc * 32 + j * 16;
            const int r  = lane >> 1, ch = (lane & 1) * 8;
            float vv[8];
            #pragma unroll
            for (int e = 0; e < 8; e++) {
                float v = buf[r * 16 + ch + e] + bias[gc + ch + e];
                if (EPI == 1) v = v * normcdff(v);     // exact GELU
                vv[e] = v;
            }
            __half2 hs[4];
            #pragma unroll
            for (int p = 0; p < 4; p++)
                hs[p] = __floats2half2_rn(vv[2 * p], vv[2 * p + 1]);
            *reinterpret_cast<int4*>(&Oh[(size_t)(gr + r) * N + gc + ch]) =
                *reinterpret_cast<int4*>(hs);
            __syncwarp();
        }
    }
}

// ---------------- per-token head-attention + residual + LN1 --------------------
// Q/K/V fp16, X fp32; output X1 as fp16 (Ah) ONLY. 256 threads per token.
__global__ void __launch_bounds__(256)
attn_ln1_kernel(const __half* __restrict__ Q, const __half* __restrict__ Kk,
                const __half* __restrict__ V, const float* __restrict__ X,
                const float* __restrict__ g1, const float* __restrict__ be1,
                __half* __restrict__ Oh)
{
    __shared__ float sq[16 * 129], sk[16 * 129], sv[16 * 129];
    __shared__ float satt[16][16];
    __shared__ float red[16];
    const int t = blockIdx.x, tid = threadIdx.x;
    const size_t base4 = (size_t)t * (DDIM / 4);
    const size_t base8 = (size_t)t * (DDIM / 8);

    // load: one int4 (8 halves) per thread per tensor
    {
        int e = tid * 8, h = e >> 7, d = e & 127, o = h * 129 + d;
        int4 qa = ((const int4*)Q)[base8 + tid];
        int4 ka = ((const int4*)Kk)[base8 + tid];
        int4 va = ((const int4*)V)[base8 + tid];
        const __half2* qh = (const __half2*)&qa;
        const __half2* kh = (const __half2*)&ka;
        const __half2* vh = (const __half2*)&va;
        #pragma unroll
        for (int p = 0; p < 4; p++) {
            float2 qf = __half22float2(qh[p]);
            float2 kf = __half22float2(kh[p]);
            float2 vf = __half22float2(vh[p]);
            sq[o + 2*p] = qf.x; sq[o + 2*p + 1] = qf.y;
            sk[o + 2*p] = kf.x; sk[o + 2*p + 1] = kf.y;
            sv[o + 2*p] = vf.x; sv[o + 2*p + 1] = vf.y;
        }
    }
    __syncthreads();

    // scores: one (h,tt) pair per thread
    {
        int h = tid >> 4, tt = tid & 15;
        const float* qp = sq + h * 129;
        const float* kp = sk + tt * 129;
        float s = 0.f;
        #pragma unroll
        for (int d = 0; d < 128; d++) s += qp[d] * kp[d];
        satt[h][tt] = s * 0.08838834764831845f;     // 1/sqrt(128)
    }
    __syncthreads();

    if (tid < 16) {
        float mx = -1e30f;
        #pragma unroll
        for (int j = 0; j < 16; j++) mx = fmaxf(mx, satt[tid][j]);
        float sum = 0.f;
        #pragma unroll
        for (int j = 0; j < 16; j++) { float e = expf(satt[tid][j] - mx); satt[tid][j] = e; sum += e; }
        float inv = 1.f / sum;
        #pragma unroll
        for (int j = 0; j < 16; j++) satt[tid][j] *= inv;
    }
    __syncthreads();

    // y + residual, 8 elems per thread (two float4 of X)
    float xp[8];
    float ls = 0.f, lq = 0.f;
    #pragma unroll
    for (int it = 0; it < 2; it++) {
        int i4 = tid * 2 + it;
        int e = i4 * 4, h = e >> 7, d = e & 127;
        float4 xv = ((const float4*)X)[base4 + i4];
        float y0 = 0.f, y1 = 0.f, y2 = 0.f, y3 = 0.f;
        #pragma unroll
        for (int tt = 0; tt < 16; tt++) {
            float p = satt[h][tt];
            const float* vp = sv + tt * 129 + d;
            y0 += p * vp[0]; y1 += p * vp[1]; y2 += p * vp[2]; y3 += p * vp[3];
        }
        float v0 = xv.x + y0, v1 = xv.y + y1, v2 = xv.z + y2, v3 = xv.w + y3;
        xp[it*4+0] = v0; xp[it*4+1] = v1; xp[it*4+2] = v2; xp[it*4+3] = v3;
        ls += v0 + v1 + v2 + v3;
        lq += v0*v0 + v1*v1 + v2*v2 + v3*v3;
    }
    #pragma unroll
    for (int off = 16; off; off >>= 1) {
        ls += __shfl_xor_sync(0xffffffffu, ls, off);
        lq += __shfl_xor_sync(0xffffffffu, lq, off);
    }
    if ((tid & 31) == 0) { red[tid >> 5] = ls; red[8 + (tid >> 5)] = lq; }
    __syncthreads();
    float S = 0.f, Qs = 0.f;
    #pragma unroll
    for (int w = 0; w < 8; w++) { S += red[w]; Qs += red[8 + w]; }
    float mean = S * (1.0f / DDIM);
    float var  = Qs * (1.0f / DDIM) - mean * mean;
    float inv  = rsqrtf(var + 1e-5f);

    // normalize + write fp16 (one int4 of 8 halves)
    __half2 hs[4];
    #pragma unroll
    for (int it = 0; it < 2; it++) {
        int i4 = tid * 2 + it;
        float4 g = ((const float4*)g1)[i4];
        float4 be = ((const float4*)be1)[i4];
        float v0 = (xp[it*4+0] - mean) * inv * g.x + be.x;
        float v1 = (xp[it*4+1] - mean) * inv * g.y + be.y;
        float v2 = (xp[it*4+2] - mean) * inv * g.z + be.z;
        float v3 = (xp[it*4+3] - mean) * inv * g.w + be.w;
        hs[it*2+0] = __floats2half2_rn(v0, v1);
        hs[it*2+1] = __floats2half2_rn(v2, v3);
    }
    *reinterpret_cast<int4*>(&Oh[(size_t)t * DDIM + tid * 8]) =
        *reinterpret_cast<int4*>(hs);
}

// ---------------- out = LN(A_half + B_half) * g + beta -------------------------
__global__ void __launch_bounds__(256)
add_ln_kernel(const __half* __restrict__ A, const __half* __restrict__ Bv,
              const float* __restrict__ g, const float* __restrict__ be,
              float* __restrict__ out)
{
    __shared__ float red[16];
    const int t = blockIdx.x, tid = threadIdx.x;
    const size_t base4 = (size_t)t * (DDIM / 4);
    const size_t base8 = (size_t)t * (DDIM / 8);

    int4 aa = ((const int4*)A)[base8 + tid];
    int4 ba = ((const int4*)Bv)[base8 + tid];
    const __half2* ah = (const __half2*)&aa;
    const __half2* bh = (const __half2*)&ba;
    float xp[8];
    float ls = 0.f, lq = 0.f;
    #pragma unroll
    for (int p = 0; p < 4; p++) {
        float2 af = __half22float2(ah[p]);
        float2 bf = __half22float2(bh[p]);
        float v0 = af.x + bf.x, v1 = af.y + bf.y;
        xp[2*p] = v0; xp[2*p+1] = v1;
        ls += v0 + v1;
        lq += v0*v0 + v1*v1;
    }
    #pragma unroll
    for (int off = 16; off; off >>= 1) {
        ls += __shfl_xor_sync(0xffffffffu, ls, off);
        lq += __shfl_xor_sync(0xffffffffu, lq, off);
    }
    if ((tid & 31) == 0) { red[tid >> 5] = ls; red[8 + (tid >> 5)] = lq; }
    __syncthreads();
    float S = 0.f, Qs = 0.f;
    #pragma unroll
    for (int w = 0; w < 8; w++) { S += red[w]; Qs += red[8 + w]; }
    float mean = S * (1.0f / DDIM);
    float var  = Qs * (1.0f / DDIM) - mean * mean;
    float inv  = rsqrtf(var + 1e-5f);
    #pragma unroll
    for (int it = 0; it < 2; it++) {
        int i4 = tid * 2 + it;
        float4 gg = ((const float4*)g)[i4];
        float4 be4 = ((const float4*)be)[i4];
        float4 v;
        v.x = (xp[it*4+0] - mean) * inv * gg.x + be4.x;
        v.y = (xp[it*4+1] - mean) * inv * gg.y + be4.y;
        v.z = (xp[it*4+2] - mean) * inv * gg.z + be4.z;
        v.w = (xp[it*4+3] - mean) * inv * gg.w + be4.w;
        ((float4*)out)[base4 + i4] = v;
    }
}

// ---------------- host orchestration -------------------------------------------
extern "C" void kernel_launch(void* const* d_in, const int* in_sizes, int n_in,
                              void* d_out, int out_size)
{
    const float* X     = (const float*)d_in[0];
    const float* Wq    = (const float*)d_in[1];
    const float* bq    = (const float*)d_in[2];
    const float* Wk    = (const float*)d_in[3];
    const float* bk    = (const float*)d_in[4];
    const float* Wv    = (const float*)d_in[5];
    const float* bv    = (const float*)d_in[6];
    const float* g1    = (const float*)d_in[7];
    const float* beta1 = (const float*)d_in[8];
    const float* W1    = (const float*)d_in[9];
    const float* b1    = (const float*)d_in[10];
    const float* W2    = (const float*)d_in[11];
    const float* b2    = (const float*)d_in[12];
    const float* g2    = (const float*)d_in[13];
    const float* beta2 = (const float*)d_in[14];
    float* out = (float*)d_out;

    __half *Ah, *Hh, *Wf, *Qh, *Kh, *Vh;
    cudaGetSymbolAddress((void**)&Ah, g_Ah);
    cudaGetSymbolAddress((void**)&Hh, g_Hh);
    cudaGetSymbolAddress((void**)&Wf, g_Wf);
    cudaGetSymbolAddress((void**)&Qh, g_Qh);
    cudaGetSymbolAddress((void**)&Kh, g_Kh);
    cudaGetSymbolAddress((void**)&Vh, g_Vh);

    cudaFuncSetAttribute(gemm_fp16<0>, cudaFuncAttributeMaxDynamicSharedMemorySize, GEMM_SMEM);
    cudaFuncSetAttribute(gemm_fp16<1>, cudaFuncAttributeMaxDynamicSharedMemorySize, GEMM_SMEM);

    // launch 0: all converts fused (X + 5 weights)
    {
        int gx = (MROWS * DDIM / 4 + 255) / 256;
        dim3 gs(gx, 6);
        split_all_kernel<<<gs, 256>>>(X, Wq, Wk, Wv, W1, W2, Ah, Wf);
    }

    dim3 gg(DDIM / BN, MROWS / BM);   // (16, 128) = 2048 CTAs
    // launches 1..3
    gemm_fp16<0><<<gg, 256, GEMM_SMEM>>>(Ah, Wf + 0 * WSZ, bq, Qh);
    gemm_fp16<0><<<gg, 256, GEMM_SMEM>>>(Ah, Wf + 1 * WSZ, bk, Kh);
    gemm_fp16<0><<<gg, 256, GEMM_SMEM>>>(Ah, Wf + 2 * WSZ, bv, Vh);
    // launch 4: attn + LN1 -> X1 stored fp16 in Ah
    attn_ln1_kernel<<<MROWS, 256>>>(Qh, Kh, Vh, X, g1, beta1, Ah);
    // launch 5  <-- ncu -s 5 -c 1 captures THIS (FFN GEMM + GELU epilogue)
    gemm_fp16<1><<<gg, 256, GEMM_SMEM>>>(Ah, Wf + 3 * WSZ, b1, Hh);
    // launch 6  (y2 reuses Qh)
    gemm_fp16<0><<<gg, 256, GEMM_SMEM>>>(Hh, Wf + 4 * WSZ, b2, Qh);
    // launch 7
    add_ln_kernel<<<MROWS, 256>>>(Ah, Qh, g2, beta2, out);
}